// round 1
// baseline (speedup 1.0000x reference)
#include <cuda_runtime.h>
#include <math.h>

#define B 32
#define Q 1000
#define G 64

// Scratch (no cudaMalloc allowed): cost stored TRANSPOSED as [B][G][Q]
__device__ float g_cost[B * G * Q];
__device__ int   g_pred_idx[B * G];   // pred_idx[b][g] = matched query index

// ---------------------------------------------------------------------------
// GIoU exactly matching the reference formula (clips + epsilons)
// ---------------------------------------------------------------------------
__device__ __forceinline__ float giou_f(float ax1, float ay1, float ax2, float ay2,
                                        float bx1, float by1, float bx2, float by2) {
    float ix1 = fmaxf(ax1, bx1), iy1 = fmaxf(ay1, by1);
    float ix2 = fminf(ax2, bx2), iy2 = fminf(ay2, by2);
    float inter  = fmaxf(ix2 - ix1, 0.f) * fmaxf(iy2 - iy1, 0.f);
    float area_a = fmaxf(ax2 - ax1, 0.f) * fmaxf(ay2 - ay1, 0.f);
    float area_b = fmaxf(bx2 - bx1, 0.f) * fmaxf(by2 - by1, 0.f);
    float uni = area_a + area_b - inter + 1e-6f;
    float iou = inter / uni;
    float ex1 = fminf(ax1, bx1), ey1 = fminf(ay1, by1);
    float ex2 = fmaxf(ax2, bx2), ey2 = fmaxf(ay2, by2);
    float enc = fmaxf(fmaxf(ex2 - ex1, 0.f) * fmaxf(ey2 - ey1, 0.f), 1e-6f);
    return iou - (enc - uni) / enc;
}

// ---------------------------------------------------------------------------
// Kernel 1: cost matrix, written transposed: g_cost[b][g][q]
// cost = -prob0 + 5*L1 - 2*giou
// ---------------------------------------------------------------------------
__global__ void cost_kernel(const float* __restrict__ pb,   // [B,Q,4]
                            const float* __restrict__ pl,   // [B,Q,2]
                            const float* __restrict__ gb) { // [B,G,4]
    int b = blockIdx.y;
    int q = blockIdx.x * blockDim.x + threadIdx.x;

    __shared__ float sgt[G * 4];
    for (int i = threadIdx.x; i < G * 4; i += blockDim.x)
        sgt[i] = gb[b * G * 4 + i];
    __syncthreads();

    if (q >= Q) return;

    const float4 p4 = *reinterpret_cast<const float4*>(pb + ((size_t)b * Q + q) * 4);
    float l0 = pl[((size_t)b * Q + q) * 2 + 0];
    float l1 = pl[((size_t)b * Q + q) * 2 + 1];
    float mx = fmaxf(l0, l1);
    float lse = mx + logf(expf(l0 - mx) + expf(l1 - mx));
    float prob0 = expf(l0 - lse);
    float base = -prob0;   // COST_CLASS = 1

    float* crow = g_cost + (size_t)b * G * Q;
#pragma unroll 4
    for (int g = 0; g < G; g++) {
        float gx1 = sgt[g * 4 + 0], gy1 = sgt[g * 4 + 1];
        float gx2 = sgt[g * 4 + 2], gy2 = sgt[g * 4 + 3];
        float l1c = fabsf(p4.x - gx1) + fabsf(p4.y - gy1) +
                    fabsf(p4.z - gx2) + fabsf(p4.w - gy2);
        float gi = giou_f(p4.x, p4.y, p4.z, p4.w, gx1, gy1, gx2, gy2);
        crow[(size_t)g * Q + q] = base + 5.0f * l1c - 2.0f * gi;
    }
}

// ---------------------------------------------------------------------------
// Kernel 2: Hungarian (JV shortest augmenting path) per batch, on the
// transposed 64x1000 matrix — matches reference _lsa exactly (fp64 potentials).
// One block (256 threads) per batch.
// ---------------------------------------------------------------------------
#define HT 256
__global__ void __launch_bounds__(HT, 1) hungarian_kernel() {
    const int b   = blockIdx.x;
    const int tid = threadIdx.x;
    const float* C = g_cost + (size_t)b * G * Q;   // C[g][q], g=row (n=64), q=col (m=1000)
    const int n = G, m = Q;
    const double INF = 1e300;

    __shared__ double v[Q + 1];
    __shared__ double minv[Q + 1];
    __shared__ double u[G + 1];
    __shared__ int    way[Q + 1];
    __shared__ int    p[Q + 1];
    __shared__ unsigned char used[Q + 1];
    __shared__ double rbest[HT];
    __shared__ int    rbj[HT];
    __shared__ int    j0_sh;
    __shared__ double delta_sh;

    for (int j = tid; j <= m; j += HT) { v[j] = 0.0; p[j] = 0; }
    for (int i = tid; i <= n; i += HT) u[i] = 0.0;
    __syncthreads();

    for (int i = 1; i <= n; i++) {
        if (tid == 0) { p[0] = i; j0_sh = 0; }
        for (int j = tid; j <= m; j += HT) { minv[j] = INF; used[j] = 0; }
        __syncthreads();

        while (true) {
            int j0 = j0_sh;
            if (tid == 0) used[j0] = 1;
            __syncthreads();

            int i0 = p[j0];
            double ui0 = u[i0];
            const float* crow = C + (size_t)(i0 - 1) * m;

            // fused minv update + local argmin over this thread's columns
            double best = INF; int bestj = m + 1;
            for (int j = 1 + tid; j <= m; j += HT) {
                if (!used[j]) {
                    double cur = (double)crow[j - 1] - ui0 - v[j];
                    if (cur < minv[j]) { minv[j] = cur; way[j] = j0; }
                    double mv = minv[j];
                    if (mv < best) { best = mv; bestj = j; }
                }
            }
            rbest[tid] = best; rbj[tid] = bestj;
            __syncthreads();
            // tree reduce with numpy-argmin tie-break (smallest index)
            for (int s = HT / 2; s > 0; s >>= 1) {
                if (tid < s) {
                    double ob = rbest[tid + s]; int oj = rbj[tid + s];
                    if (ob < rbest[tid] || (ob == rbest[tid] && oj < rbj[tid])) {
                        rbest[tid] = ob; rbj[tid] = oj;
                    }
                }
                __syncthreads();
            }
            if (tid == 0) { delta_sh = rbest[0]; j0_sh = rbj[0]; }
            __syncthreads();

            double delta = delta_sh;
            int j1 = j0_sh;
            // potentials update (p[j] distinct over used j -> race-free)
            for (int j = tid; j <= m; j += HT) {
                if (used[j]) { u[p[j]] += delta; v[j] -= delta; }
                else         { minv[j] -= delta; }
            }
            __syncthreads();
            if (p[j1] == 0) break;
        }

        // augment (serial, thread 0)
        if (tid == 0) {
            int j0 = j0_sh;
            while (j0) { int jp = way[j0]; p[j0] = p[jp]; j0 = jp; }
        }
        __syncthreads();
    }

    // extract: pred_idx[b][row-1] = col-1
    for (int j = 1 + tid; j <= m; j += HT) {
        int pi = p[j];
        if (pi > 0) g_pred_idx[b * G + (pi - 1)] = j - 1;
    }
}

// ---------------------------------------------------------------------------
// Kernel 3: losses (single block).
// class loss = sum_b [ (0.1*sum_q nll1 + sum_matched (nll0 - 0.1*nll1)) / wt_sum ]
// wt_sum = 64*1.0 + 936*0.1 = 157.6
// ---------------------------------------------------------------------------
#define LT 512
__global__ void __launch_bounds__(LT, 1) losses_kernel(
        const float* __restrict__ pb, const float* __restrict__ pl,
        const float* __restrict__ gb, float* __restrict__ out) {
    int tid = threadIdx.x;
    __shared__ double cls[B];
    __shared__ double red[LT];
    if (tid < B) cls[tid] = 0.0;
    __syncthreads();

    // phase 1: base class term (all labels = 1): 0.1 * nll1
    {
        int b = tid >> 4;          // 16 threads per batch
        int lane = tid & 15;
        double s = 0.0;
        for (int q = lane; q < Q; q += 16) {
            float l0 = pl[((size_t)b * Q + q) * 2 + 0];
            float l1 = pl[((size_t)b * Q + q) * 2 + 1];
            float mx = fmaxf(l0, l1);
            float lse = mx + logf(expf(l0 - mx) + expf(l1 - mx));
            s += 0.1 * (double)(lse - l1);   // nll1 = -(l1 - lse)
        }
        atomicAdd(&cls[b], s);
    }

    // phase 2: matched pairs
    double bbox = 0.0, giou_s = 0.0;
    for (int k = tid; k < B * G; k += LT) {
        int b = k >> 6, g = k & 63;
        int q = g_pred_idx[b * G + g];
        const float4 mp = *reinterpret_cast<const float4*>(pb + ((size_t)b * Q + q) * 4);
        const float4 mg = *reinterpret_cast<const float4*>(gb + ((size_t)b * G + g) * 4);
        bbox += (double)(fabsf(mp.x - mg.x) + fabsf(mp.y - mg.y) +
                         fabsf(mp.z - mg.z) + fabsf(mp.w - mg.w));
        giou_s += 1.0 - (double)giou_f(mp.x, mp.y, mp.z, mp.w, mg.x, mg.y, mg.z, mg.w);
        // class correction for matched query: label 0, weight 1.0 replaces 0.1*nll1
        float l0 = pl[((size_t)b * Q + q) * 2 + 0];
        float l1 = pl[((size_t)b * Q + q) * 2 + 1];
        float mx = fmaxf(l0, l1);
        float lse = mx + logf(expf(l0 - mx) + expf(l1 - mx));
        double nll0 = (double)(lse - l0);
        double nll1 = (double)(lse - l1);
        atomicAdd(&cls[b], nll0 - 0.1 * nll1);
    }
    __syncthreads();

    // reduce bbox
    red[tid] = bbox; __syncthreads();
    for (int s = LT / 2; s > 0; s >>= 1) {
        if (tid < s) red[tid] += red[tid + s];
        __syncthreads();
    }
    double bbox_tot = red[0];
    __syncthreads();
    red[tid] = giou_s; __syncthreads();
    for (int s = LT / 2; s > 0; s >>= 1) {
        if (tid < s) red[tid] += red[tid + s];
        __syncthreads();
    }
    double giou_tot = red[0];
    __syncthreads();

    if (tid == 0) {
        const double wt_sum = 64.0 * 1.0 + (double)(Q - G) * 0.1;  // 157.6
        double lcsum = 0.0;
        for (int b2 = 0; b2 < B; b2++) lcsum += cls[b2] / wt_sum;
        double lc = lcsum / (double)B;
        double num_boxes = (double)(B * G);
        double lb = bbox_tot / num_boxes;
        double lg = giou_tot / num_boxes;
        out[0] = (float)(1.0 * lc + 5.0 * lb + 2.0 * lg);
        out[1] = (float)lc;
        out[2] = (float)lb;
        out[3] = (float)lg;
    }
}

// ---------------------------------------------------------------------------
extern "C" void kernel_launch(void* const* d_in, const int* in_sizes, int n_in,
                              void* d_out, int out_size) {
    const float* pred_boxes  = (const float*)d_in[0];  // [32,1000,4]
    const float* pred_logits = (const float*)d_in[1];  // [32,1000,2]
    const float* gt_boxes    = (const float*)d_in[2];  // [32,64,4]
    float* out = (float*)d_out;

    dim3 cgrid((Q + 127) / 128, B);
    cost_kernel<<<cgrid, 128>>>(pred_boxes, pred_logits, gt_boxes);
    hungarian_kernel<<<B, HT>>>();
    losses_kernel<<<1, LT>>>(pred_boxes, pred_logits, gt_boxes, out);
}

// round 2
// speedup vs baseline: 1.0019x; 1.0019x over previous
#include <cuda_runtime.h>
#include <math.h>

#define B 32
#define Q 1000
#define G 64
#define HT 128

// Scratch (no cudaMalloc allowed)
__device__ float  g_cost[B * G * Q];   // cost transposed: [b][g][q]
__device__ double g_part[B * 3];       // per-batch {cls, bbox, giou} partials

// ---------------------------------------------------------------------------
// GIoU exactly matching the reference formula (clips + epsilons)
// ---------------------------------------------------------------------------
__device__ __forceinline__ float giou_f(float ax1, float ay1, float ax2, float ay2,
                                        float bx1, float by1, float bx2, float by2) {
    float ix1 = fmaxf(ax1, bx1), iy1 = fmaxf(ay1, by1);
    float ix2 = fminf(ax2, bx2), iy2 = fminf(ay2, by2);
    float inter  = fmaxf(ix2 - ix1, 0.f) * fmaxf(iy2 - iy1, 0.f);
    float area_a = fmaxf(ax2 - ax1, 0.f) * fmaxf(ay2 - ay1, 0.f);
    float area_b = fmaxf(bx2 - bx1, 0.f) * fmaxf(by2 - by1, 0.f);
    float uni = area_a + area_b - inter + 1e-6f;
    float iou = inter / uni;
    float ex1 = fminf(ax1, bx1), ey1 = fminf(ay1, by1);
    float ex2 = fmaxf(ax2, bx2), ey2 = fmaxf(ey2 = fmaxf(ay2, by2), ey2); // placeholder removed below
    return 0.f; // never used (specialized below)
}

// NOTE: the helper above got mangled during edit; use this correct one:
__device__ __forceinline__ float giou_ok(float ax1, float ay1, float ax2, float ay2,
                                         float bx1, float by1, float bx2, float by2) {
    float ix1 = fmaxf(ax1, bx1), iy1 = fmaxf(ay1, by1);
    float ix2 = fminf(ax2, bx2), iy2 = fminf(ay2, by2);
    float inter  = fmaxf(ix2 - ix1, 0.f) * fmaxf(iy2 - iy1, 0.f);
    float area_a = fmaxf(ax2 - ax1, 0.f) * fmaxf(ay2 - ay1, 0.f);
    float area_b = fmaxf(bx2 - bx1, 0.f) * fmaxf(by2 - by1, 0.f);
    float uni = area_a + area_b - inter + 1e-6f;
    float iou = inter / uni;
    float ex1 = fminf(ax1, bx1), ey1 = fminf(ay1, by1);
    float ex2 = fmaxf(ax2, bx2), ey2 = fmaxf(ay2, by2);
    float enc = fmaxf(fmaxf(ex2 - ex1, 0.f) * fmaxf(ey2 - ey1, 0.f), 1e-6f);
    return iou - (enc - uni) / enc;
}

// ---------------------------------------------------------------------------
// Kernel 1: cost matrix, transposed write g_cost[b][g][q].
// Parallel over q AND g-chunks: grid (8, 8, B), 128 thr; 8 g's per thread.
// ---------------------------------------------------------------------------
__global__ void cost_kernel(const float* __restrict__ pb,   // [B,Q,4]
                            const float* __restrict__ pl,   // [B,Q,2]
                            const float* __restrict__ gb) { // [B,G,4]
    int b  = blockIdx.z;
    int q  = blockIdx.x * blockDim.x + threadIdx.x;
    int g0 = blockIdx.y * 8;
    if (q >= Q) return;

    const float4 p4 = *reinterpret_cast<const float4*>(pb + ((size_t)b * Q + q) * 4);
    float l0 = pl[((size_t)b * Q + q) * 2 + 0];
    float l1 = pl[((size_t)b * Q + q) * 2 + 1];
    float mx = fmaxf(l0, l1);
    float lse = mx + logf(expf(l0 - mx) + expf(l1 - mx));
    float base = -expf(l0 - lse);   // -prob0, COST_CLASS = 1

    float* crow = g_cost + (size_t)b * G * Q;
#pragma unroll
    for (int k = 0; k < 8; k++) {
        int g = g0 + k;
        const float4 g4 = *reinterpret_cast<const float4*>(gb + ((size_t)b * G + g) * 4);
        float l1c = fabsf(p4.x - g4.x) + fabsf(p4.y - g4.y) +
                    fabsf(p4.z - g4.z) + fabsf(p4.w - g4.w);
        float gi = giou_ok(p4.x, p4.y, p4.z, p4.w, g4.x, g4.y, g4.z, g4.w);
        crow[(size_t)g * Q + q] = base + 5.0f * l1c - 2.0f * gi;
    }
}

// ---------------------------------------------------------------------------
// Kernel 2: Hungarian (lazy scipy-style shortest augmenting path, fp64
// potentials) on the 64x1000 transposed cost, one block/batch, 128 threads.
// ONE __syncthreads per inner iteration (owner-private used/spc/path +
// parity-double-buffered cross-warp reduction). Losses fused in the tail.
// ---------------------------------------------------------------------------
__global__ void __launch_bounds__(HT, 1) hungarian_kernel(
        const float* __restrict__ pb, const float* __restrict__ pl,
        const float* __restrict__ gb) {
    const int b = blockIdx.x;
    const int tid = threadIdx.x;
    const int lane = tid & 31, wid = tid >> 5;
    const float* C = g_cost + (size_t)b * G * Q;   // C[g][q]
    const double INF = 1e300;

    __shared__ double v_sh[Q];
    __shared__ double spc[Q];        // shortest path costs (absolute)
    __shared__ double u_sh[G];
    __shared__ int    path[Q];       // predecessor row for column j
    __shared__ int    row4col[Q];
    __shared__ int    col4row[G];
    __shared__ unsigned char used[Q];
    __shared__ int    sc_list[G + 2];
    __shared__ double red_val[2][4];
    __shared__ int    red_idx[2][4];
    __shared__ double rbuf[HT];

    for (int j = tid; j < Q; j += HT) { v_sh[j] = 0.0; row4col[j] = -1; }
    if (tid < G) u_sh[tid] = 0.0;
    __syncthreads();

    for (int cur = 0; cur < G; cur++) {
        // reset owner-private state (no barrier needed: owner-only access,
        // prior augmentation's consumers finished before its end barrier)
        for (int j = tid; j < Q; j += HT) { spc[j] = INF; used[j] = 0; }

        int i = cur, sc_cnt = 0, par = 0, sink = -1;
        double minVal = 0.0;

        while (true) {
            double ui = u_sh[i];
            const float* crow = C + (size_t)i * Q;

            double best = INF; int bestj = 0x7FFFFFFF;
            for (int j = tid; j < Q; j += HT) {
                if (!used[j]) {
                    double r = minVal + (double)__ldg(&crow[j]) - ui - v_sh[j];
                    if (r < spc[j]) { spc[j] = r; path[j] = i; }
                    double s = spc[j];
                    if (s < best) { best = s; bestj = j; }  // ascending j => ties keep smallest
                }
            }
            // warp argmin (smallest-index tie-break)
#pragma unroll
            for (int off = 16; off > 0; off >>= 1) {
                double ob = __shfl_down_sync(0xffffffffu, best, off);
                int    oj = __shfl_down_sync(0xffffffffu, bestj, off);
                if (ob < best || (ob == best && oj < bestj)) { best = ob; bestj = oj; }
            }
            if (lane == 0) { red_val[par][wid] = best; red_idx[par][wid] = bestj; }
            __syncthreads();
            // all threads combine 4 slots identically (bit-identical result)
            best = red_val[par][0]; bestj = red_idx[par][0];
#pragma unroll
            for (int k = 1; k < 4; k++) {
                double ob = red_val[par][k]; int oj = red_idx[par][k];
                if (ob < best || (ob == best && oj < bestj)) { best = ob; bestj = oj; }
            }
            minVal = best;
            int j1 = bestj;
            if ((j1 & (HT - 1)) == tid) used[j1] = 1;   // owner flags it; only owner reads it
            if (tid == 0) sc_list[sc_cnt] = j1;
            sc_cnt++;
            par ^= 1;

            int nr = row4col[j1];
            if (nr < 0) { sink = j1; break; }
            i = nr;
        }

        // end-of-augmentation potential updates + augment (O(path), serial)
        if (tid == 0) {
            u_sh[cur] += minVal;
            for (int k = 0; k < sc_cnt; k++) {
                int j = sc_list[k];
                double d = minVal - spc[j];
                int r = row4col[j];
                if (r >= 0) u_sh[r] += d;
                v_sh[j] -= d;
            }
            int j = sink;
            while (true) {
                int i2 = path[j];
                row4col[j] = i2;
                int t = col4row[i2];
                col4row[i2] = j;
                j = t;
                if (i2 == cur) break;
            }
        }
        __syncthreads();
    }

    // ------------------- fused per-batch losses -------------------
    double cls = 0.0, bbox = 0.0, gio = 0.0;
    for (int q = tid; q < Q; q += HT) {
        float l0 = pl[((size_t)b * Q + q) * 2 + 0];
        float l1 = pl[((size_t)b * Q + q) * 2 + 1];
        float mx = fmaxf(l0, l1);
        float lse = mx + logf(expf(l0 - mx) + expf(l1 - mx));
        cls += 0.1 * (double)(lse - l1);          // base: all labels = 1
    }
    if (tid < G) {
        int g = tid;
        int q = col4row[g];
        const float4 mp = *reinterpret_cast<const float4*>(pb + ((size_t)b * Q + q) * 4);
        const float4 mg = *reinterpret_cast<const float4*>(gb + ((size_t)b * G + g) * 4);
        bbox = (double)(fabsf(mp.x - mg.x) + fabsf(mp.y - mg.y) +
                        fabsf(mp.z - mg.z) + fabsf(mp.w - mg.w));
        gio = 1.0 - (double)giou_ok(mp.x, mp.y, mp.z, mp.w, mg.x, mg.y, mg.z, mg.w);
        float l0 = pl[((size_t)b * Q + q) * 2 + 0];
        float l1 = pl[((size_t)b * Q + q) * 2 + 1];
        float mx = fmaxf(l0, l1);
        float lse = mx + logf(expf(l0 - mx) + expf(l1 - mx));
        cls += (double)(lse - l0) - 0.1 * (double)(lse - l1);   // matched correction
    }
    // block reductions (3x)
    rbuf[tid] = cls; __syncthreads();
    for (int s = HT / 2; s > 0; s >>= 1) { if (tid < s) rbuf[tid] += rbuf[tid + s]; __syncthreads(); }
    double cls_t = rbuf[0]; __syncthreads();
    rbuf[tid] = bbox; __syncthreads();
    for (int s = HT / 2; s > 0; s >>= 1) { if (tid < s) rbuf[tid] += rbuf[tid + s]; __syncthreads(); }
    double bbox_t = rbuf[0]; __syncthreads();
    rbuf[tid] = gio; __syncthreads();
    for (int s = HT / 2; s > 0; s >>= 1) { if (tid < s) rbuf[tid] += rbuf[tid + s]; __syncthreads(); }
    double gio_t = rbuf[0];

    if (tid == 0) {
        g_part[b * 3 + 0] = cls_t;
        g_part[b * 3 + 1] = bbox_t;
        g_part[b * 3 + 2] = gio_t;
    }
}

// ---------------------------------------------------------------------------
// Kernel 3: finalize (1 warp)
// ---------------------------------------------------------------------------
__global__ void finalize_kernel(float* __restrict__ out) {
    int lane = threadIdx.x;
    double cls = 0.0, bb = 0.0, gi = 0.0;
    if (lane < B) {
        cls = g_part[lane * 3 + 0];
        bb  = g_part[lane * 3 + 1];
        gi  = g_part[lane * 3 + 2];
    }
#pragma unroll
    for (int off = 16; off > 0; off >>= 1) {
        cls += __shfl_down_sync(0xffffffffu, cls, off);
        bb  += __shfl_down_sync(0xffffffffu, bb, off);
        gi  += __shfl_down_sync(0xffffffffu, gi, off);
    }
    if (lane == 0) {
        const double wt_sum = 64.0 * 1.0 + (double)(Q - G) * 0.1;  // 157.6
        double lc = (cls / wt_sum) / (double)B;
        double nb = (double)(B * G);
        double lb = bb / nb;
        double lg = gi / nb;
        out[0] = (float)(1.0 * lc + 5.0 * lb + 2.0 * lg);
        out[1] = (float)lc;
        out[2] = (float)lb;
        out[3] = (float)lg;
    }
}

// ---------------------------------------------------------------------------
extern "C" void kernel_launch(void* const* d_in, const int* in_sizes, int n_in,
                              void* d_out, int out_size) {
    const float* pred_boxes  = (const float*)d_in[0];  // [32,1000,4]
    const float* pred_logits = (const float*)d_in[1];  // [32,1000,2]
    const float* gt_boxes    = (const float*)d_in[2];  // [32,64,4]
    float* out = (float*)d_out;

    dim3 cgrid((Q + 127) / 128, G / 8, B);
    cost_kernel<<<cgrid, 128>>>(pred_boxes, pred_logits, gt_boxes);
    hungarian_kernel<<<B, HT>>>(pred_boxes, pred_logits, gt_boxes);
    finalize_kernel<<<1, 32>>>(out);
}

// round 3
// speedup vs baseline: 2.4967x; 2.4919x over previous
#include <cuda_runtime.h>
#include <math.h>

#define B 32
#define Q 1000
#define G 64
#define HT 128

// Scratch (no cudaMalloc allowed)
__device__ float  g_cost[B * G * Q];   // cost transposed: [b][g][q]
__device__ double g_part[B * 3];       // per-batch {cls, bbox, giou} partials

// ---------------------------------------------------------------------------
// GIoU exactly matching the reference formula (clips + epsilons)
// ---------------------------------------------------------------------------
__device__ __forceinline__ float giou_ok(float ax1, float ay1, float ax2, float ay2,
                                         float bx1, float by1, float bx2, float by2) {
    float ix1 = fmaxf(ax1, bx1), iy1 = fmaxf(ay1, by1);
    float ix2 = fminf(ax2, bx2), iy2 = fminf(ay2, by2);
    float inter  = fmaxf(ix2 - ix1, 0.f) * fmaxf(iy2 - iy1, 0.f);
    float area_a = fmaxf(ax2 - ax1, 0.f) * fmaxf(ay2 - ay1, 0.f);
    float area_b = fmaxf(bx2 - bx1, 0.f) * fmaxf(by2 - by1, 0.f);
    float uni = area_a + area_b - inter + 1e-6f;
    float iou = inter / uni;
    float ex1 = fminf(ax1, bx1), ey1 = fminf(ay1, by1);
    float ex2 = fmaxf(ax2, bx2), ey2 = fmaxf(ay2, by2);
    float enc = fmaxf(fmaxf(ex2 - ex1, 0.f) * fmaxf(ey2 - ey1, 0.f), 1e-6f);
    return iou - (enc - uni) / enc;
}

// ---------------------------------------------------------------------------
// Kernel 1: cost matrix, transposed write g_cost[b][g][q].
// grid (8, 8, B), 128 thr; 8 g's per thread.
// ---------------------------------------------------------------------------
__global__ void cost_kernel(const float* __restrict__ pb,   // [B,Q,4]
                            const float* __restrict__ pl,   // [B,Q,2]
                            const float* __restrict__ gb) { // [B,G,4]
    int b  = blockIdx.z;
    int q  = blockIdx.x * blockDim.x + threadIdx.x;
    int g0 = blockIdx.y * 8;
    if (q >= Q) return;

    const float4 p4 = *reinterpret_cast<const float4*>(pb + ((size_t)b * Q + q) * 4);
    float l0 = pl[((size_t)b * Q + q) * 2 + 0];
    float l1 = pl[((size_t)b * Q + q) * 2 + 1];
    // softmax(l)[0] == sigmoid(l0 - l1): one expf instead of 2 expf + logf
    float base = -1.0f / (1.0f + expf(l1 - l0));   // -prob0, COST_CLASS = 1

    float* crow = g_cost + (size_t)b * G * Q;
#pragma unroll
    for (int k = 0; k < 8; k++) {
        int g = g0 + k;
        const float4 g4 = *reinterpret_cast<const float4*>(gb + ((size_t)b * G + g) * 4);
        float l1c = fabsf(p4.x - g4.x) + fabsf(p4.y - g4.y) +
                    fabsf(p4.z - g4.z) + fabsf(p4.w - g4.w);
        float gi = giou_ok(p4.x, p4.y, p4.z, p4.w, g4.x, g4.y, g4.z, g4.w);
        crow[(size_t)g * Q + q] = base + 5.0f * l1c - 2.0f * gi;
    }
}

// ---------------------------------------------------------------------------
// Kernel 2: Hungarian with JV column-reduction preprocessing.
//   phase 1: u[g] = min_q C[g,q] (warp-parallel row minima), v = 0
//   phase 2: greedy-assign each row its argmin column if free (~60/64 rows)
//   phase 3: lazy shortest-augmenting-path (fp64 duals) for leftover rows
// One block per batch, 128 threads. Losses fused in the tail.
// ---------------------------------------------------------------------------
__global__ void __launch_bounds__(HT, 1) hungarian_kernel(
        const float* __restrict__ pb, const float* __restrict__ pl,
        const float* __restrict__ gb) {
    const int b = blockIdx.x;
    const int tid = threadIdx.x;
    const int lane = tid & 31, wid = tid >> 5;
    const float* C = g_cost + (size_t)b * G * Q;   // C[g][q]
    const double INF = 1e300;

    __shared__ double v_sh[Q];
    __shared__ double spc[Q];        // shortest path costs (absolute)
    __shared__ double u_sh[G];
    __shared__ int    path[Q];       // predecessor row for column j
    __shared__ int    row4col[Q];
    __shared__ int    col4row[G];
    __shared__ unsigned char used[Q];
    __shared__ int    sc_list[Q];
    __shared__ double red_val[2][4];
    __shared__ int    red_idx[2][4];
    __shared__ double rbuf[HT];
    __shared__ float  umin[G];
    __shared__ int    uarg[G];

    for (int j = tid; j < Q; j += HT) { v_sh[j] = 0.0; row4col[j] = -1; }
    __syncthreads();

    // ---- phase 1: row minima (warp w handles rows w, w+4, ...) ----
    for (int r = wid; r < G; r += 4) {
        const float* crow = C + (size_t)r * Q;
        float best = 3.0e38f; int bj = Q;
        for (int j = lane; j < Q; j += 32) {
            float c = __ldg(&crow[j]);
            if (c < best) { best = c; bj = j; }
        }
#pragma unroll
        for (int off = 16; off > 0; off >>= 1) {
            float ob = __shfl_down_sync(0xffffffffu, best, off);
            int   oj = __shfl_down_sync(0xffffffffu, bj, off);
            if (ob < best || (ob == best && oj < bj)) { best = ob; bj = oj; }
        }
        if (lane == 0) { umin[r] = best; uarg[r] = bj; }
    }
    __syncthreads();
    if (tid < G) u_sh[tid] = (double)umin[tid];
    // ---- phase 2: greedy tight-edge assignment (serial, trivial) ----
    if (tid == 0) {
        for (int r = 0; r < G; r++) {
            int j = uarg[r];
            if (row4col[j] < 0) { row4col[j] = r; col4row[r] = j; }
            else                 col4row[r] = -1;
        }
    }
    __syncthreads();

    // ---- phase 3: SAP for unassigned rows only ----
    for (int cur = 0; cur < G; cur++) {
        if (col4row[cur] >= 0) continue;

        for (int j = tid; j < Q; j += HT) { spc[j] = INF; used[j] = 0; }

        int i = cur, sc_cnt = 0, par = 0, sink = -1;
        double minVal = 0.0;

        while (true) {
            double ui = u_sh[i];
            const float* crow = C + (size_t)i * Q;

            double best = INF; int bestj = 0x7FFFFFFF;
            for (int j = tid; j < Q; j += HT) {
                if (!used[j]) {
                    double r = minVal + (double)__ldg(&crow[j]) - ui - v_sh[j];
                    if (r < spc[j]) { spc[j] = r; path[j] = i; }
                    double s = spc[j];
                    if (s < best) { best = s; bestj = j; }
                }
            }
#pragma unroll
            for (int off = 16; off > 0; off >>= 1) {
                double ob = __shfl_down_sync(0xffffffffu, best, off);
                int    oj = __shfl_down_sync(0xffffffffu, bestj, off);
                if (ob < best || (ob == best && oj < bestj)) { best = ob; bestj = oj; }
            }
            if (lane == 0) { red_val[par][wid] = best; red_idx[par][wid] = bestj; }
            __syncthreads();
            best = red_val[par][0]; bestj = red_idx[par][0];
#pragma unroll
            for (int k = 1; k < 4; k++) {
                double ob = red_val[par][k]; int oj = red_idx[par][k];
                if (ob < best || (ob == best && oj < bestj)) { best = ob; bestj = oj; }
            }
            minVal = best;
            int j1 = bestj;
            if ((j1 & (HT - 1)) == tid) used[j1] = 1;   // owner-private flag
            if (tid == 0) sc_list[sc_cnt] = j1;
            sc_cnt++;
            par ^= 1;

            int nr = row4col[j1];
            if (nr < 0) { sink = j1; break; }
            i = nr;
        }

        if (tid == 0) {
            u_sh[cur] += minVal;
            for (int k = 0; k < sc_cnt; k++) {
                int j = sc_list[k];
                double d = minVal - spc[j];
                int r = row4col[j];
                if (r >= 0) u_sh[r] += d;
                v_sh[j] -= d;
            }
            int j = sink;
            while (true) {
                int i2 = path[j];
                row4col[j] = i2;
                int t = col4row[i2];
                col4row[i2] = j;
                j = t;
                if (i2 == cur) break;
            }
        }
        __syncthreads();
    }

    // ------------------- fused per-batch losses -------------------
    double cls = 0.0, bbox = 0.0, gio = 0.0;
    for (int q = tid; q < Q; q += HT) {
        float l0 = pl[((size_t)b * Q + q) * 2 + 0];
        float l1 = pl[((size_t)b * Q + q) * 2 + 1];
        float mx = fmaxf(l0, l1);
        float lse = mx + logf(expf(l0 - mx) + expf(l1 - mx));
        cls += 0.1 * (double)(lse - l1);          // base: all labels = 1
    }
    if (tid < G) {
        int g = tid;
        int q = col4row[g];
        const float4 mp = *reinterpret_cast<const float4*>(pb + ((size_t)b * Q + q) * 4);
        const float4 mg = *reinterpret_cast<const float4*>(gb + ((size_t)b * G + g) * 4);
        bbox = (double)(fabsf(mp.x - mg.x) + fabsf(mp.y - mg.y) +
                        fabsf(mp.z - mg.z) + fabsf(mp.w - mg.w));
        gio = 1.0 - (double)giou_ok(mp.x, mp.y, mp.z, mp.w, mg.x, mg.y, mg.z, mg.w);
        float l0 = pl[((size_t)b * Q + q) * 2 + 0];
        float l1 = pl[((size_t)b * Q + q) * 2 + 1];
        float mx = fmaxf(l0, l1);
        float lse = mx + logf(expf(l0 - mx) + expf(l1 - mx));
        cls += (double)(lse - l0) - 0.1 * (double)(lse - l1);   // matched correction
    }
    rbuf[tid] = cls; __syncthreads();
    for (int s = HT / 2; s > 0; s >>= 1) { if (tid < s) rbuf[tid] += rbuf[tid + s]; __syncthreads(); }
    double cls_t = rbuf[0]; __syncthreads();
    rbuf[tid] = bbox; __syncthreads();
    for (int s = HT / 2; s > 0; s >>= 1) { if (tid < s) rbuf[tid] += rbuf[tid + s]; __syncthreads(); }
    double bbox_t = rbuf[0]; __syncthreads();
    rbuf[tid] = gio; __syncthreads();
    for (int s = HT / 2; s > 0; s >>= 1) { if (tid < s) rbuf[tid] += rbuf[tid + s]; __syncthreads(); }
    double gio_t = rbuf[0];

    if (tid == 0) {
        g_part[b * 3 + 0] = cls_t;
        g_part[b * 3 + 1] = bbox_t;
        g_part[b * 3 + 2] = gio_t;
    }
}

// ---------------------------------------------------------------------------
// Kernel 3: finalize (1 warp)
// ---------------------------------------------------------------------------
__global__ void finalize_kernel(float* __restrict__ out) {
    int lane = threadIdx.x;
    double cls = 0.0, bb = 0.0, gi = 0.0;
    if (lane < B) {
        cls = g_part[lane * 3 + 0];
        bb  = g_part[lane * 3 + 1];
        gi  = g_part[lane * 3 + 2];
    }
#pragma unroll
    for (int off = 16; off > 0; off >>= 1) {
        cls += __shfl_down_sync(0xffffffffu, cls, off);
        bb  += __shfl_down_sync(0xffffffffu, bb, off);
        gi  += __shfl_down_sync(0xffffffffu, gi, off);
    }
    if (lane == 0) {
        const double wt_sum = 64.0 * 1.0 + (double)(Q - G) * 0.1;  // 157.6
        double lc = (cls / wt_sum) / (double)B;
        double nb = (double)(B * G);
        double lb = bb / nb;
        double lg = gi / nb;
        out[0] = (float)(1.0 * lc + 5.0 * lb + 2.0 * lg);
        out[1] = (float)lc;
        out[2] = (float)lb;
        out[3] = (float)lg;
    }
}

// ---------------------------------------------------------------------------
extern "C" void kernel_launch(void* const* d_in, const int* in_sizes, int n_in,
                              void* d_out, int out_size) {
    const float* pred_boxes  = (const float*)d_in[0];  // [32,1000,4]
    const float* pred_logits = (const float*)d_in[1];  // [32,1000,2]
    const float* gt_boxes    = (const float*)d_in[2];  // [32,64,4]
    float* out = (float*)d_out;

    dim3 cgrid((Q + 127) / 128, G / 8, B);
    cost_kernel<<<cgrid, 128>>>(pred_boxes, pred_logits, gt_boxes);
    hungarian_kernel<<<B, HT>>>(pred_boxes, pred_logits, gt_boxes);
    finalize_kernel<<<1, 32>>>(out);
}

// round 4
// speedup vs baseline: 3.5896x; 1.4377x over previous
#include <cuda_runtime.h>
#include <math.h>
#include <float.h>

#define B 32
#define Q 1000
#define G 64
#define HT 256

// Scratch (no cudaMalloc allowed)
__device__ float  g_cost[B * G * Q];   // cost transposed: [b][g][q]
__device__ double g_part[B * 3];       // per-batch {cls, bbox, giou}
__device__ int    g_done = 0;

// ---------------------------------------------------------------------------
__device__ __forceinline__ float giou_ok(float ax1, float ay1, float ax2, float ay2,
                                         float bx1, float by1, float bx2, float by2) {
    float ix1 = fmaxf(ax1, bx1), iy1 = fmaxf(ay1, by1);
    float ix2 = fminf(ax2, bx2), iy2 = fminf(ay2, by2);
    float inter  = fmaxf(ix2 - ix1, 0.f) * fmaxf(iy2 - iy1, 0.f);
    float area_a = fmaxf(ax2 - ax1, 0.f) * fmaxf(ay2 - ay1, 0.f);
    float area_b = fmaxf(bx2 - bx1, 0.f) * fmaxf(by2 - by1, 0.f);
    float uni = area_a + area_b - inter + 1e-6f;
    float iou = inter / uni;
    float ex1 = fminf(ax1, bx1), ey1 = fminf(ay1, by1);
    float ex2 = fmaxf(ax2, bx2), ey2 = fmaxf(ay2, by2);
    float enc = fmaxf(fmaxf(ex2 - ex1, 0.f) * fmaxf(ey2 - ey1, 0.f), 1e-6f);
    return iou - (enc - uni) / enc;
}

// ---------------------------------------------------------------------------
// Kernel 1: cost matrix, transposed write g_cost[b][g][q].
// grid (8, 16, B), 128 thr; 4 g's per thread.
// ---------------------------------------------------------------------------
__global__ void cost_kernel(const float* __restrict__ pb,
                            const float* __restrict__ pl,
                            const float* __restrict__ gb) {
    int b  = blockIdx.z;
    int q  = blockIdx.x * blockDim.x + threadIdx.x;
    int g0 = blockIdx.y * 4;
    if (q >= Q) return;

    const float4 p4 = *reinterpret_cast<const float4*>(pb + ((size_t)b * Q + q) * 4);
    float l0 = pl[((size_t)b * Q + q) * 2 + 0];
    float l1 = pl[((size_t)b * Q + q) * 2 + 1];
    float base = -1.0f / (1.0f + expf(l1 - l0));   // -softmax[0]

    float* crow = g_cost + (size_t)b * G * Q;
#pragma unroll
    for (int k = 0; k < 4; k++) {
        int g = g0 + k;
        const float4 g4 = *reinterpret_cast<const float4*>(gb + ((size_t)b * G + g) * 4);
        float l1c = fabsf(p4.x - g4.x) + fabsf(p4.y - g4.y) +
                    fabsf(p4.z - g4.z) + fabsf(p4.w - g4.w);
        float gi = giou_ok(p4.x, p4.y, p4.z, p4.w, g4.x, g4.y, g4.z, g4.w);
        crow[(size_t)g * Q + q] = base + 5.0f * l1c - 2.0f * gi;
    }
}

// ---------------------------------------------------------------------------
// Kernel 2: full LAPJV-style Hungarian, fp32 duals.
//   P1: row minima (u init), P2: greedy tight-edge assign,
//   P3: augmenting row reduction (warp 0), P4: SAP for leftovers,
//   tail: fused losses + last-block finalize.
// ---------------------------------------------------------------------------
__global__ void __launch_bounds__(HT, 1) hungarian_kernel(
        const float* __restrict__ pb, const float* __restrict__ pl,
        const float* __restrict__ gb, float* __restrict__ out) {
    const int b = blockIdx.x;
    const int tid = threadIdx.x;
    const int lane = tid & 31, wid = tid >> 5;
    const float* C = g_cost + (size_t)b * G * Q;   // C[g][q]
    const float FINF = FLT_MAX;

    __shared__ float  v_sh[Q];
    __shared__ float  spc[Q];
    __shared__ float  u_sh[G];
    __shared__ int    path[Q];
    __shared__ int    row4col[Q];
    __shared__ int    col4row[G];
    __shared__ unsigned char used[Q];
    __shared__ int    sc_list[Q];
    __shared__ float  red_val[2][8];
    __shared__ int    red_idx[2][8];
    __shared__ double rbuf[HT];
    __shared__ float  umin[G];
    __shared__ int    uarg[G];
    __shared__ int    freerows[4 * G];
    __shared__ int    nfree_sh;

    for (int j = tid; j < Q; j += HT) { v_sh[j] = 0.0f; row4col[j] = -1; }
    __syncthreads();

    // ---- P1: row minima (warp w handles rows w, w+8, ...) ----
    for (int r = wid; r < G; r += 8) {
        const float* crow = C + (size_t)r * Q;
        float best = FINF; int bj = Q;
        for (int j = lane; j < Q; j += 32) {
            float c = __ldg(&crow[j]);
            if (c < best) { best = c; bj = j; }
        }
#pragma unroll
        for (int off = 16; off > 0; off >>= 1) {
            float ob = __shfl_down_sync(0xffffffffu, best, off);
            int   oj = __shfl_down_sync(0xffffffffu, bj, off);
            if (ob < best || (ob == best && oj < bj)) { best = ob; bj = oj; }
        }
        if (lane == 0) { umin[r] = best; uarg[r] = bj; }
    }
    __syncthreads();
    if (tid < G) u_sh[tid] = umin[tid];
    // ---- P2: greedy tight-edge assignment ----
    if (tid == 0) {
        int nf = 0;
        for (int r = 0; r < G; r++) {
            int j = uarg[r];
            if (row4col[j] < 0) { row4col[j] = r; col4row[r] = j; }
            else { col4row[r] = -1; freerows[nf++] = r; }
        }
        nfree_sh = nf;
    }
    __syncthreads();

    // ---- P3: augmenting row reduction (warp 0 only) ----
    if (wid == 0) {
        int idx = 0, cnt = nfree_sh, iters = 0;
        const int cap = 4 * G - 4;
        while (idx < cnt && iters < cap) {
            iters++;
            int i = freerows[idx]; idx++;
            const float* crow = C + (size_t)i * Q;
            // (m1,j1,m2,j2) over reduced costs C[i][j] - v[j]
            float m1 = FINF, m2 = FINF; int j1 = Q, j2 = Q;
            for (int j = lane; j < Q; j += 32) {
                float red = __ldg(&crow[j]) - v_sh[j];
                if (red < m1) { m2 = m1; j2 = j1; m1 = red; j1 = j; }
                else if (red < m2) { m2 = red; j2 = j; }
            }
#pragma unroll
            for (int off = 16; off > 0; off >>= 1) {
                float b1 = __shfl_xor_sync(0xffffffffu, m1, off);
                int   bj1 = __shfl_xor_sync(0xffffffffu, j1, off);
                float b2 = __shfl_xor_sync(0xffffffffu, m2, off);
                int   bj2 = __shfl_xor_sync(0xffffffffu, j2, off);
                if (b1 < m1 || (b1 == m1 && bj1 < j1)) {
                    // other's m1 becomes m1; new m2 = min(old m1, other's m2)
                    if (m1 < b2 || (m1 == b2 && j1 < bj2)) { m2 = m1; j2 = j1; }
                    else { m2 = b2; j2 = bj2; }
                    m1 = b1; j1 = bj1;
                } else {
                    if (b1 < m2 || (b1 == m2 && bj1 < j2)) { m2 = b1; j2 = bj1; }
                }
            }
            bool strict = (m1 < m2);
            int jt = j1;
            int i0 = row4col[jt];
            if (!strict && i0 >= 0 && j2 < Q) { jt = j2; i0 = row4col[jt]; }
            // register-state updates mirrored on all lanes
            if (i0 >= 0) {
                if (strict) { idx--; }           // reprocess kicked row immediately
                else if (cnt < 4 * G) { cnt++; } // append
            }
            if (lane == 0) {
                u_sh[i] = m2;
                if (strict) v_sh[jt] -= (m2 - m1);
                row4col[jt] = i; col4row[i] = jt;
                if (i0 >= 0) {
                    col4row[i0] = -1;
                    if (strict) freerows[idx] = i0;
                    else if (cnt - 1 < 4 * G) freerows[cnt - 1] = i0;
                }
            }
            __syncwarp();
        }
    }
    __syncthreads();

    // ---- P4: SAP (fp32) for any remaining free rows ----
    for (int cur = 0; cur < G; cur++) {
        if (col4row[cur] >= 0) continue;

        for (int j = tid; j < Q; j += HT) { spc[j] = FINF; used[j] = 0; }

        int i = cur, sc_cnt = 0, par = 0, sink = -1;
        float minVal = 0.0f;

        while (true) {
            float ui = u_sh[i];
            const float* crow = C + (size_t)i * Q;

            float best = FINF; int bestj = 0x7FFFFFFF;
            for (int j = tid; j < Q; j += HT) {
                if (!used[j]) {
                    float r = minVal + __ldg(&crow[j]) - ui - v_sh[j];
                    if (r < spc[j]) { spc[j] = r; path[j] = i; }
                    float s = spc[j];
                    if (s < best) { best = s; bestj = j; }
                }
            }
#pragma unroll
            for (int off = 16; off > 0; off >>= 1) {
                float ob = __shfl_down_sync(0xffffffffu, best, off);
                int   oj = __shfl_down_sync(0xffffffffu, bestj, off);
                if (ob < best || (ob == best && oj < bestj)) { best = ob; bestj = oj; }
            }
            if (lane == 0) { red_val[par][wid] = best; red_idx[par][wid] = bestj; }
            __syncthreads();
            best = red_val[par][0]; bestj = red_idx[par][0];
#pragma unroll
            for (int k = 1; k < 8; k++) {
                float ob = red_val[par][k]; int oj = red_idx[par][k];
                if (ob < best || (ob == best && oj < bestj)) { best = ob; bestj = oj; }
            }
            minVal = best;
            int j1 = bestj;
            if ((j1 & (HT - 1)) == tid) used[j1] = 1;   // owner-private flag
            if (tid == 0) sc_list[sc_cnt] = j1;
            sc_cnt++;
            par ^= 1;

            int nr = row4col[j1];
            if (nr < 0) { sink = j1; break; }
            i = nr;
        }

        if (tid == 0) {
            u_sh[cur] += minVal;
            for (int k = 0; k < sc_cnt; k++) {
                int j = sc_list[k];
                float d = minVal - spc[j];
                int r = row4col[j];
                if (r >= 0) u_sh[r] += d;
                v_sh[j] -= d;
            }
            int j = sink;
            while (true) {
                int i2 = path[j];
                row4col[j] = i2;
                int t = col4row[i2];
                col4row[i2] = j;
                j = t;
                if (i2 == cur) break;
            }
        }
        __syncthreads();
    }

    // ------------------- fused per-batch losses (fp64) -------------------
    double cls = 0.0, bbox = 0.0, gio = 0.0;
    for (int q = tid; q < Q; q += HT) {
        float l0 = pl[((size_t)b * Q + q) * 2 + 0];
        float l1 = pl[((size_t)b * Q + q) * 2 + 1];
        float mx = fmaxf(l0, l1);
        float lse = mx + logf(expf(l0 - mx) + expf(l1 - mx));
        cls += 0.1 * (double)(lse - l1);
    }
    if (tid < G) {
        int g = tid;
        int q = col4row[g];
        const float4 mp = *reinterpret_cast<const float4*>(pb + ((size_t)b * Q + q) * 4);
        const float4 mg = *reinterpret_cast<const float4*>(gb + ((size_t)b * G + g) * 4);
        bbox = (double)(fabsf(mp.x - mg.x) + fabsf(mp.y - mg.y) +
                        fabsf(mp.z - mg.z) + fabsf(mp.w - mg.w));
        gio = 1.0 - (double)giou_ok(mp.x, mp.y, mp.z, mp.w, mg.x, mg.y, mg.z, mg.w);
        float l0 = pl[((size_t)b * Q + q) * 2 + 0];
        float l1 = pl[((size_t)b * Q + q) * 2 + 1];
        float mx = fmaxf(l0, l1);
        float lse = mx + logf(expf(l0 - mx) + expf(l1 - mx));
        cls += (double)(lse - l0) - 0.1 * (double)(lse - l1);
    }
    rbuf[tid] = cls; __syncthreads();
    for (int s = HT / 2; s > 0; s >>= 1) { if (tid < s) rbuf[tid] += rbuf[tid + s]; __syncthreads(); }
    double cls_t = rbuf[0]; __syncthreads();
    rbuf[tid] = bbox; __syncthreads();
    for (int s = HT / 2; s > 0; s >>= 1) { if (tid < s) rbuf[tid] += rbuf[tid + s]; __syncthreads(); }
    double bbox_t = rbuf[0]; __syncthreads();
    rbuf[tid] = gio; __syncthreads();
    for (int s = HT / 2; s > 0; s >>= 1) { if (tid < s) rbuf[tid] += rbuf[tid + s]; __syncthreads(); }
    double gio_t = rbuf[0];

    if (tid == 0) {
        g_part[b * 3 + 0] = cls_t;
        g_part[b * 3 + 1] = bbox_t;
        g_part[b * 3 + 2] = gio_t;
        __threadfence();
        int prev = atomicAdd(&g_done, 1);
        if (prev == B - 1) {          // last block finalizes
            g_done = 0;               // reset for next graph replay
            __threadfence();
            double csum = 0.0, bsum = 0.0, gsum = 0.0;
            for (int k = 0; k < B; k++) {
                csum += g_part[k * 3 + 0];
                bsum += g_part[k * 3 + 1];
                gsum += g_part[k * 3 + 2];
            }
            const double wt_sum = 64.0 + (double)(Q - G) * 0.1;  // 157.6
            double lc = (csum / wt_sum) / (double)B;
            double nb = (double)(B * G);
            double lb = bsum / nb;
            double lg = gsum / nb;
            out[0] = (float)(1.0 * lc + 5.0 * lb + 2.0 * lg);
            out[1] = (float)lc;
            out[2] = (float)lb;
            out[3] = (float)lg;
        }
    }
}

// ---------------------------------------------------------------------------
extern "C" void kernel_launch(void* const* d_in, const int* in_sizes, int n_in,
                              void* d_out, int out_size) {
    const float* pred_boxes  = (const float*)d_in[0];  // [32,1000,4]
    const float* pred_logits = (const float*)d_in[1];  // [32,1000,2]
    const float* gt_boxes    = (const float*)d_in[2];  // [32,64,4]
    float* out = (float*)d_out;

    dim3 cgrid((Q + 127) / 128, G / 4, B);
    cost_kernel<<<cgrid, 128>>>(pred_boxes, pred_logits, gt_boxes);
    hungarian_kernel<<<B, HT>>>(pred_boxes, pred_logits, gt_boxes, out);
}

// round 5
// speedup vs baseline: 3.9176x; 1.0914x over previous
#include <cuda_runtime.h>
#include <math.h>
#include <float.h>

#define B 32
#define Q 1000
#define G 64
#define HT 256
#define KC 64           // candidates per row (2 per lane)
#define TCAP 2048       // touched-list capacity (overflow -> fallback)
#define FULLM 0xffffffffu

// Scratch (no cudaMalloc allowed)
__device__ float  g_cost[B * G * Q];   // cost transposed: [b][g][q]
__device__ double g_part[B * 3];       // per-batch {cls, bbox, giou}
__device__ int    g_done = 0;

// ---------------------------------------------------------------------------
__device__ __forceinline__ float giou_ok(float ax1, float ay1, float ax2, float ay2,
                                         float bx1, float by1, float bx2, float by2) {
    float ix1 = fmaxf(ax1, bx1), iy1 = fmaxf(ay1, by1);
    float ix2 = fminf(ax2, bx2), iy2 = fminf(ay2, by2);
    float inter  = fmaxf(ix2 - ix1, 0.f) * fmaxf(iy2 - iy1, 0.f);
    float area_a = fmaxf(ax2 - ax1, 0.f) * fmaxf(ay2 - ay1, 0.f);
    float area_b = fmaxf(bx2 - bx1, 0.f) * fmaxf(by2 - by1, 0.f);
    float uni = area_a + area_b - inter + 1e-6f;
    float iou = inter / uni;
    float ex1 = fminf(ax1, bx1), ey1 = fminf(ay1, by1);
    float ex2 = fmaxf(ax2, bx2), ey2 = fmaxf(ay2, by2);
    float enc = fmaxf(fmaxf(ex2 - ex1, 0.f) * fmaxf(ey2 - ey1, 0.f), 1e-6f);
    return iou - (enc - uni) / enc;
}

// ---------------------------------------------------------------------------
// Kernel 1: cost matrix, transposed write g_cost[b][g][q].
// ---------------------------------------------------------------------------
__global__ void cost_kernel(const float* __restrict__ pb,
                            const float* __restrict__ pl,
                            const float* __restrict__ gb) {
    int b  = blockIdx.z;
    int q  = blockIdx.x * blockDim.x + threadIdx.x;
    int g0 = blockIdx.y * 4;
    if (q >= Q) return;

    const float4 p4 = *reinterpret_cast<const float4*>(pb + ((size_t)b * Q + q) * 4);
    float l0 = pl[((size_t)b * Q + q) * 2 + 0];
    float l1 = pl[((size_t)b * Q + q) * 2 + 1];
    float base = -1.0f / (1.0f + __expf(l1 - l0));   // -softmax[0]

    float* crow = g_cost + (size_t)b * G * Q;
#pragma unroll
    for (int k = 0; k < 4; k++) {
        int g = g0 + k;
        const float4 g4 = *reinterpret_cast<const float4*>(gb + ((size_t)b * G + g) * 4);
        float l1c = fabsf(p4.x - g4.x) + fabsf(p4.y - g4.y) +
                    fabsf(p4.z - g4.z) + fabsf(p4.w - g4.w);
        float gi = giou_ok(p4.x, p4.y, p4.z, p4.w, g4.x, g4.y, g4.z, g4.w);
        crow[(size_t)g * Q + q] = base + 5.0f * l1c - 2.0f * gi;
    }
}

// ---------------------------------------------------------------------------
// Kernel 2: candidate-pruned LAPJV + certificate + full fallback + losses.
// ---------------------------------------------------------------------------
__global__ void __launch_bounds__(HT, 1) hungarian_kernel(
        const float* __restrict__ pb, const float* __restrict__ pl,
        const float* __restrict__ gb, float* __restrict__ out) {
    const int b = blockIdx.x;
    const int tid = threadIdx.x;
    const int lane = tid & 31, wid = tid >> 5;
    const float* C = g_cost + (size_t)b * G * Q;
    const float FINF = FLT_MAX;

    __shared__ float  v_sh[Q];
    __shared__ float  spc[Q];
    __shared__ float  u_sh[G];
    __shared__ short  path[Q];
    __shared__ short  row4col[Q];
    __shared__ short  col4row[G];
    __shared__ unsigned char used[Q];
    __shared__ short  touched[TCAP];
    __shared__ float  cand_cost[G * KC];
    __shared__ short  cand_col[G * KC];
    __shared__ float  T_sh[G];
    __shared__ float  umin[G];
    __shared__ int    uarg[G];
    __shared__ short  freerows[4 * G];
    __shared__ float  red_val[2][8];
    __shared__ int    red_idx[2][8];
    __shared__ double wsum[8][3];
    __shared__ int    nfree_sh, nt_sh, fail_sh;

    for (int j = tid; j < Q; j += HT) {
        v_sh[j] = 0.f; row4col[j] = -1; spc[j] = FINF; used[j] = 0;
    }
    if (tid == 0) fail_sh = 0;
    __syncthreads();

    // ---- P1: per-row scan: per-lane top-2 -> candidates; T = min excluded ----
    for (int r = wid; r < G; r += 8) {
        const float* crow = C + (size_t)r * Q;
        float m1 = FINF, m2 = FINF, m3 = FINF;
        int j1 = Q, j2 = Q;
        for (int j = lane; j < Q; j += 32) {
            float c = __ldg(&crow[j]);
            if (c < m1)      { m3 = m2; m2 = m1; j2 = j1; m1 = c; j1 = j; }
            else if (c < m2) { m3 = m2; m2 = c; j2 = j; }
            else if (c < m3) { m3 = c; }
        }
        cand_cost[r * KC + lane]      = m1;
        cand_col [r * KC + lane]      = (short)j1;
        cand_cost[r * KC + 32 + lane] = m2;
        cand_col [r * KC + 32 + lane] = (short)j2;
        float t3 = m3;
        float bm = m1; int bj = j1;
#pragma unroll
        for (int off = 16; off > 0; off >>= 1) {
            t3 = fminf(t3, __shfl_down_sync(FULLM, t3, off));
            float om = __shfl_down_sync(FULLM, bm, off);
            int   oj = __shfl_down_sync(FULLM, bj, off);
            if (om < bm || (om == bm && oj < bj)) { bm = om; bj = oj; }
        }
        if (lane == 0) { T_sh[r] = t3; umin[r] = bm; uarg[r] = bj; }
    }
    __syncthreads();
    if (tid < G) u_sh[tid] = umin[tid];
    __syncthreads();

    // =================== single-warp sparse matcher (warp 0) ===================
    if (wid == 0) {
        // ---- P2: greedy tight-edge assignment ----
        if (lane == 0) {
            int nf = 0;
            for (int r = 0; r < G; r++) {
                int j = uarg[r];
                if (row4col[j] < 0) { row4col[j] = (short)r; col4row[r] = (short)j; }
                else { col4row[r] = -1; freerows[nf++] = (short)r; }
            }
            nfree_sh = nf;
        }
        __syncwarp();

        // ---- P3: augmenting row reduction on candidates ----
        {
            int idx = 0, cnt = nfree_sh, iters = 0;
            while (idx < cnt && iters < 256) {
                iters++;
                int i = freerows[idx]; idx++;
                int ja = cand_col[i * KC + lane];
                int jb = cand_col[i * KC + 32 + lane];
                float ra = cand_cost[i * KC + lane]      - v_sh[ja];
                float rb = cand_cost[i * KC + 32 + lane] - v_sh[jb];
                float m1, m2; int j1, j2;
                if (ra < rb || (ra == rb && ja < jb)) { m1 = ra; j1 = ja; m2 = rb; j2 = jb; }
                else                                   { m1 = rb; j1 = jb; m2 = ra; j2 = ja; }
#pragma unroll
                for (int off = 16; off > 0; off >>= 1) {
                    float b1 = __shfl_xor_sync(FULLM, m1, off);
                    int   bj1 = __shfl_xor_sync(FULLM, j1, off);
                    float b2 = __shfl_xor_sync(FULLM, m2, off);
                    int   bj2 = __shfl_xor_sync(FULLM, j2, off);
                    if (b1 < m1 || (b1 == m1 && bj1 < j1)) {
                        if (m1 < b2 || (m1 == b2 && j1 < bj2)) { m2 = m1; j2 = j1; }
                        else { m2 = b2; j2 = bj2; }
                        m1 = b1; j1 = bj1;
                    } else {
                        if (b1 < m2 || (b1 == m2 && bj1 < j2)) { m2 = b1; j2 = bj1; }
                    }
                }
                bool strict = (m1 < m2);
                int jt = j1;
                int i0 = row4col[jt];
                if (!strict && i0 >= 0) { jt = j2; i0 = row4col[jt]; }
                if (i0 >= 0) {
                    if (strict) idx--;
                    else if (cnt < 4 * G) cnt++;
                }
                if (lane == 0) {
                    u_sh[i] = m2;
                    if (strict) v_sh[jt] -= (m2 - m1);
                    row4col[jt] = (short)i; col4row[i] = (short)jt;
                    if (i0 >= 0) {
                        col4row[i0] = -1;
                        if (strict) freerows[idx] = (short)i0;
                        else if (cnt - 1 < 4 * G) freerows[cnt - 1] = (short)i0;
                    }
                }
                __syncwarp();
            }
        }

        // ---- P4: sparse SAP on candidates ----
        for (int cur = 0; cur < G; cur++) {
            if (fail_sh) break;
            if (col4row[cur] >= 0) continue;
            if (lane == 0) nt_sh = 0;
            __syncwarp();

            int i = cur, sink = -1;
            float minVal = 0.f;

            while (true) {
                float ui = u_sh[i];
#pragma unroll
                for (int h = 0; h < 2; h++) {
                    int t = lane + 32 * h;
                    int j = cand_col[i * KC + t];
                    if (!used[j]) {
                        float r = minVal + cand_cost[i * KC + t] - ui - v_sh[j];
                        if (r < spc[j]) {
                            if (spc[j] == FINF) {
                                int slot = atomicAdd(&nt_sh, 1);
                                if (slot < TCAP) touched[slot] = (short)j;
                                else fail_sh = 1;
                            }
                            spc[j] = r; path[j] = (short)i;
                        }
                    }
                }
                __syncwarp();
                if (fail_sh) break;
                int nt = nt_sh;
                float best = FINF; int bestj = 0x7FFFFFFF;
                for (int t = lane; t < nt; t += 32) {
                    int j = touched[t];
                    if (!used[j]) {
                        float s = spc[j];
                        if (s < best || (s == best && j < bestj)) { best = s; bestj = j; }
                    }
                }
#pragma unroll
                for (int off = 16; off > 0; off >>= 1) {
                    float ob = __shfl_down_sync(FULLM, best, off);
                    int   oj = __shfl_down_sync(FULLM, bestj, off);
                    if (ob < best || (ob == best && oj < bestj)) { best = ob; bestj = oj; }
                }
                best  = __shfl_sync(FULLM, best, 0);
                bestj = __shfl_sync(FULLM, bestj, 0);
                if (best == FINF) { fail_sh = 1; break; }   // safety (unreachable)
                minVal = best;
                int j1 = bestj;
                if (lane == 0) used[j1] = 1;
                __syncwarp();
                int nr = row4col[j1];
                if (nr < 0) { sink = j1; break; }
                i = nr;
            }
            if (fail_sh) break;

            // duals (parallel, race-free: distinct rows per used col) BEFORE augment
            int nt = nt_sh;
            if (lane == 0) u_sh[cur] += minVal;
            for (int t = lane; t < nt; t += 32) {
                int j = touched[t];
                if (used[j]) {
                    float d = minVal - spc[j];
                    int r = row4col[j];
                    if (r >= 0) u_sh[r] += d;
                    v_sh[j] -= d;
                }
            }
            __syncwarp();
            if (lane == 0) {
                int j = sink;
                while (true) {
                    int i2 = path[j];
                    row4col[j] = (short)i2;
                    int tcol = col4row[i2];
                    col4row[i2] = (short)j;
                    j = tcol;
                    if (i2 == cur) break;
                }
            }
            __syncwarp();
            // cleanup touched for next augmentation
            for (int t = lane; t < nt && t < TCAP; t += 32) {
                int j = touched[t]; spc[j] = FINF; used[j] = 0;
            }
            __syncwarp();
        }

        // ---- certificate: u[i] <= T[i] => sparse optimum == global optimum ----
        if (!fail_sh) {
            bool bad = false;
            for (int r = lane; r < G; r += 32)
                if (u_sh[r] > T_sh[r]) bad = true;
            if (__any_sync(FULLM, bad) && lane == 0) fail_sh = 1;
        }
    }
    __syncthreads();

    // =================== fallback: full-matrix SAP (rare/never) ===================
    if (fail_sh) {
        for (int j = tid; j < Q; j += HT) {
            v_sh[j] = 0.f; row4col[j] = -1; spc[j] = FINF; used[j] = 0;
        }
        if (tid < G) { col4row[tid] = -1; u_sh[tid] = umin[tid]; }
        __syncthreads();
        if (tid == 0) {
            for (int r = 0; r < G; r++) {
                int j = uarg[r];
                if (row4col[j] < 0) { row4col[j] = (short)r; col4row[r] = (short)j; }
                else col4row[r] = -1;
            }
        }
        __syncthreads();

        for (int cur = 0; cur < G; cur++) {
            if (col4row[cur] >= 0) continue;
            int i = cur, par = 0, sink = -1;
            float minVal = 0.f;

            while (true) {
                float ui = u_sh[i];
                const float* crow = C + (size_t)i * Q;
                float best = FINF; int bestj = 0x7FFFFFFF;
                for (int j = tid; j < Q; j += HT) {
                    if (!used[j]) {
                        float r = minVal + __ldg(&crow[j]) - ui - v_sh[j];
                        if (r < spc[j]) { spc[j] = r; path[j] = (short)i; }
                        float s = spc[j];
                        if (s < best) { best = s; bestj = j; }
                    }
                }
#pragma unroll
                for (int off = 16; off > 0; off >>= 1) {
                    float ob = __shfl_down_sync(FULLM, best, off);
                    int   oj = __shfl_down_sync(FULLM, bestj, off);
                    if (ob < best || (ob == best && oj < bestj)) { best = ob; bestj = oj; }
                }
                if (lane == 0) { red_val[par][wid] = best; red_idx[par][wid] = bestj; }
                __syncthreads();
                best = red_val[par][0]; bestj = red_idx[par][0];
#pragma unroll
                for (int k = 1; k < 8; k++) {
                    float ob = red_val[par][k]; int oj = red_idx[par][k];
                    if (ob < best || (ob == best && oj < bestj)) { best = ob; bestj = oj; }
                }
                minVal = best;
                int j1 = bestj;
                if ((j1 & (HT - 1)) == tid) used[j1] = 1;
                par ^= 1;
                __syncthreads();     // make used[j1] visible before next relax
                int nr = row4col[j1];
                if (nr < 0) { sink = j1; break; }
                i = nr;
            }

            // duals (parallel) before augment
            for (int j = tid; j < Q; j += HT) {
                if (used[j]) {
                    float d = minVal - spc[j];
                    int r = row4col[j];
                    if (r >= 0) u_sh[r] += d;
                    v_sh[j] -= d;
                }
            }
            __syncthreads();
            if (tid == 0) {
                u_sh[cur] += minVal;
                int j = sink;
                while (true) {
                    int i2 = path[j];
                    row4col[j] = (short)i2;
                    int tcol = col4row[i2];
                    col4row[i2] = (short)j;
                    j = tcol;
                    if (i2 == cur) break;
                }
            }
            __syncthreads();
            for (int j = tid; j < Q; j += HT) { spc[j] = FINF; used[j] = 0; }
            __syncthreads();
        }
    }

    // =================== fused per-batch losses (fp64) ===================
    double cls = 0.0, bbox = 0.0, gio = 0.0;
    for (int q = tid; q < Q; q += HT) {
        float l0 = pl[((size_t)b * Q + q) * 2 + 0];
        float l1 = pl[((size_t)b * Q + q) * 2 + 1];
        float mx = fmaxf(l0, l1);
        float lse = mx + logf(expf(l0 - mx) + expf(l1 - mx));
        cls += 0.1 * (double)(lse - l1);
    }
    if (tid < G) {
        int g = tid;
        int q = col4row[g];
        const float4 mp = *reinterpret_cast<const float4*>(pb + ((size_t)b * Q + q) * 4);
        const float4 mg = *reinterpret_cast<const float4*>(gb + ((size_t)b * G + g) * 4);
        bbox = (double)(fabsf(mp.x - mg.x) + fabsf(mp.y - mg.y) +
                        fabsf(mp.z - mg.z) + fabsf(mp.w - mg.w));
        gio = 1.0 - (double)giou_ok(mp.x, mp.y, mp.z, mp.w, mg.x, mg.y, mg.z, mg.w);
        float l0 = pl[((size_t)b * Q + q) * 2 + 0];
        float l1 = pl[((size_t)b * Q + q) * 2 + 1];
        float mx = fmaxf(l0, l1);
        float lse = mx + logf(expf(l0 - mx) + expf(l1 - mx));
        cls += (double)(lse - l0) - 0.1 * (double)(lse - l1);
    }
#pragma unroll
    for (int off = 16; off > 0; off >>= 1) {
        cls  += __shfl_down_sync(FULLM, cls, off);
        bbox += __shfl_down_sync(FULLM, bbox, off);
        gio  += __shfl_down_sync(FULLM, gio, off);
    }
    if (lane == 0) { wsum[wid][0] = cls; wsum[wid][1] = bbox; wsum[wid][2] = gio; }
    __syncthreads();

    if (tid == 0) {
        double cls_t = 0.0, bbox_t = 0.0, gio_t = 0.0;
        for (int w = 0; w < 8; w++) {
            cls_t += wsum[w][0]; bbox_t += wsum[w][1]; gio_t += wsum[w][2];
        }
        g_part[b * 3 + 0] = cls_t;
        g_part[b * 3 + 1] = bbox_t;
        g_part[b * 3 + 2] = gio_t;
        __threadfence();
        int prev = atomicAdd(&g_done, 1);
        if (prev == B - 1) {
            g_done = 0;
            __threadfence();
            double csum = 0.0, bsum = 0.0, gsum = 0.0;
            for (int k = 0; k < B; k++) {
                csum += g_part[k * 3 + 0];
                bsum += g_part[k * 3 + 1];
                gsum += g_part[k * 3 + 2];
            }
            const double wt_sum = 64.0 + (double)(Q - G) * 0.1;  // 157.6
            double lc = (csum / wt_sum) / (double)B;
            double nb = (double)(B * G);
            double lb = bsum / nb;
            double lg = gsum / nb;
            out[0] = (float)(1.0 * lc + 5.0 * lb + 2.0 * lg);
            out[1] = (float)lc;
            out[2] = (float)lb;
            out[3] = (float)lg;
        }
    }
}

// ---------------------------------------------------------------------------
extern "C" void kernel_launch(void* const* d_in, const int* in_sizes, int n_in,
                              void* d_out, int out_size) {
    const float* pred_boxes  = (const float*)d_in[0];  // [32,1000,4]
    const float* pred_logits = (const float*)d_in[1];  // [32,1000,2]
    const float* gt_boxes    = (const float*)d_in[2];  // [32,64,4]
    float* out = (float*)d_out;

    dim3 cgrid((Q + 127) / 128, G / 4, B);
    cost_kernel<<<cgrid, 128>>>(pred_boxes, pred_logits, gt_boxes);
    hungarian_kernel<<<B, HT>>>(pred_boxes, pred_logits, gt_boxes, out);
}

// round 6
// speedup vs baseline: 3.9193x; 1.0004x over previous
#include <cuda_runtime.h>
#include <math.h>
#include <float.h>

#define B 32
#define Q 1000
#define G 64
#define HT 256
#define KC 64           // candidates per row (2 per lane)
#define TCAP 1024       // touched-list capacity (overflow -> abort sparse, repair)
#define FULLM 0xffffffffu

// Scratch (no cudaMalloc allowed)
__device__ float  g_cost[B * G * Q];   // cost transposed: [b][g][q]
__device__ double g_part[B * 3];       // per-batch {cls, bbox, giou}
__device__ int    g_done = 0;

// ---------------------------------------------------------------------------
__device__ __forceinline__ float giou_fast(float ax1, float ay1, float ax2, float ay2,
                                           float bx1, float by1, float bx2, float by2) {
    float ix1 = fmaxf(ax1, bx1), iy1 = fmaxf(ay1, by1);
    float ix2 = fminf(ax2, bx2), iy2 = fminf(ay2, by2);
    float inter  = fmaxf(ix2 - ix1, 0.f) * fmaxf(iy2 - iy1, 0.f);
    float area_a = fmaxf(ax2 - ax1, 0.f) * fmaxf(ay2 - ay1, 0.f);
    float area_b = fmaxf(bx2 - bx1, 0.f) * fmaxf(by2 - by1, 0.f);
    float uni = area_a + area_b - inter + 1e-6f;
    float iou = __fdividef(inter, uni);
    float ex1 = fminf(ax1, bx1), ey1 = fminf(ay1, by1);
    float ex2 = fmaxf(ax2, bx2), ey2 = fmaxf(ay2, by2);
    float enc = fmaxf(fmaxf(ex2 - ex1, 0.f) * fmaxf(ey2 - ey1, 0.f), 1e-6f);
    return iou - __fdividef(enc - uni, enc);
}

// precise version for the loss (matches reference math closely)
__device__ __forceinline__ float giou_ok(float ax1, float ay1, float ax2, float ay2,
                                         float bx1, float by1, float bx2, float by2) {
    float ix1 = fmaxf(ax1, bx1), iy1 = fmaxf(ay1, by1);
    float ix2 = fminf(ax2, bx2), iy2 = fminf(ay2, by2);
    float inter  = fmaxf(ix2 - ix1, 0.f) * fmaxf(iy2 - iy1, 0.f);
    float area_a = fmaxf(ax2 - ax1, 0.f) * fmaxf(ay2 - ay1, 0.f);
    float area_b = fmaxf(bx2 - bx1, 0.f) * fmaxf(by2 - by1, 0.f);
    float uni = area_a + area_b - inter + 1e-6f;
    float iou = inter / uni;
    float ex1 = fminf(ax1, bx1), ey1 = fminf(ay1, by1);
    float ex2 = fmaxf(ax2, bx2), ey2 = fmaxf(ay2, by2);
    float enc = fmaxf(fmaxf(ex2 - ex1, 0.f) * fmaxf(ey2 - ey1, 0.f), 1e-6f);
    return iou - (enc - uni) / enc;
}

// ---------------------------------------------------------------------------
// Kernel 1: cost matrix, transposed write g_cost[b][g][q].
// ---------------------------------------------------------------------------
__global__ void cost_kernel(const float* __restrict__ pb,
                            const float* __restrict__ pl,
                            const float* __restrict__ gb) {
    int b  = blockIdx.z;
    int q  = blockIdx.x * blockDim.x + threadIdx.x;
    int g0 = blockIdx.y * 4;
    if (q >= Q) return;

    const float4 p4 = *reinterpret_cast<const float4*>(pb + ((size_t)b * Q + q) * 4);
    float l0 = pl[((size_t)b * Q + q) * 2 + 0];
    float l1 = pl[((size_t)b * Q + q) * 2 + 1];
    float base = -1.0f / (1.0f + __expf(l1 - l0));   // -softmax[0]

    float* crow = g_cost + (size_t)b * G * Q;
#pragma unroll
    for (int k = 0; k < 4; k++) {
        int g = g0 + k;
        const float4 g4 = *reinterpret_cast<const float4*>(gb + ((size_t)b * G + g) * 4);
        float l1c = fabsf(p4.x - g4.x) + fabsf(p4.y - g4.y) +
                    fabsf(p4.z - g4.z) + fabsf(p4.w - g4.w);
        float gi = giou_fast(p4.x, p4.y, p4.z, p4.w, g4.x, g4.y, g4.z, g4.w);
        crow[(size_t)g * Q + q] = base + 5.0f * l1c - 2.0f * gi;
    }
}

// ---------------------------------------------------------------------------
// Kernel 2: sparse LAPJV + exact verify-and-repair + fused losses.
// ---------------------------------------------------------------------------
__global__ void __launch_bounds__(HT, 1) hungarian_kernel(
        const float* __restrict__ pb, const float* __restrict__ pl,
        const float* __restrict__ gb, float* __restrict__ out) {
    const int b = blockIdx.x;
    const int tid = threadIdx.x;
    const int lane = tid & 31, wid = tid >> 5;
    const float* C = g_cost + (size_t)b * G * Q;
    const float FINF = FLT_MAX;

    __shared__ float  v_sh[Q];
    __shared__ float  spc[Q];
    __shared__ float  u_sh[G];
    __shared__ short  path[Q];
    __shared__ short  row4col[Q];
    __shared__ short  col4row[G];
    __shared__ unsigned char used[Q];
    __shared__ short  touched[TCAP];
    __shared__ float  cand_cost[G * KC];
    __shared__ short  cand_col[G * KC];
    __shared__ float  umin[G];      // P1 row min; reused as verify u_new
    __shared__ int    uarg[G];      // P1 argmin;  reused as verify argmin
    __shared__ short  freerows[4 * G];
    __shared__ float  red_val[2][8];
    __shared__ int    red_idx[2][8];
    __shared__ double wsum[8][3];
    __shared__ int    nfree_sh, nt_sh, fail_sh;

    for (int j = tid; j < Q; j += HT) {
        v_sh[j] = 0.f; row4col[j] = -1; spc[j] = FINF; used[j] = 0;
    }
    if (tid == 0) fail_sh = 0;
    __syncthreads();

    // ---- P1: per-row scan: per-lane top-2 -> candidates, row min/argmin ----
    for (int r = wid; r < G; r += 8) {
        const float* crow = C + (size_t)r * Q;
        float m1 = FINF, m2 = FINF;
        int j1 = Q, j2 = Q;
        for (int j = lane; j < Q; j += 32) {
            float c = __ldg(&crow[j]);
            if (c < m1)      { m2 = m1; j2 = j1; m1 = c; j1 = j; }
            else if (c < m2) { m2 = c; j2 = j; }
        }
        cand_cost[r * KC + lane]      = m1;
        cand_col [r * KC + lane]      = (short)j1;
        cand_cost[r * KC + 32 + lane] = m2;
        cand_col [r * KC + 32 + lane] = (short)j2;
        float bm = m1; int bj = j1;
#pragma unroll
        for (int off = 16; off > 0; off >>= 1) {
            float om = __shfl_down_sync(FULLM, bm, off);
            int   oj = __shfl_down_sync(FULLM, bj, off);
            if (om < bm || (om == bm && oj < bj)) { bm = om; bj = oj; }
        }
        if (lane == 0) { umin[r] = bm; uarg[r] = bj; }
    }
    __syncthreads();
    if (tid < G) u_sh[tid] = umin[tid];
    __syncthreads();

    // =================== single-warp sparse matcher (warp 0) ===================
    if (wid == 0) {
        // ---- P2: greedy tight-edge assignment ----
        if (lane == 0) {
            int nf = 0;
            for (int r = 0; r < G; r++) {
                int j = uarg[r];
                if (row4col[j] < 0) { row4col[j] = (short)r; col4row[r] = (short)j; }
                else { col4row[r] = -1; freerows[nf++] = (short)r; }
            }
            nfree_sh = nf;
        }
        __syncwarp();

        // ---- P3: augmenting row reduction on candidates ----
        {
            int idx = 0, cnt = nfree_sh, iters = 0;
            while (idx < cnt && iters < 256) {
                iters++;
                int i = freerows[idx]; idx++;
                int ja = cand_col[i * KC + lane];
                int jb = cand_col[i * KC + 32 + lane];
                float ra = cand_cost[i * KC + lane]      - v_sh[ja];
                float rb = cand_cost[i * KC + 32 + lane] - v_sh[jb];
                float m1, m2; int j1, j2;
                if (ra < rb || (ra == rb && ja < jb)) { m1 = ra; j1 = ja; m2 = rb; j2 = jb; }
                else                                   { m1 = rb; j1 = jb; m2 = ra; j2 = ja; }
#pragma unroll
                for (int off = 16; off > 0; off >>= 1) {
                    float b1 = __shfl_xor_sync(FULLM, m1, off);
                    int   bj1 = __shfl_xor_sync(FULLM, j1, off);
                    float b2 = __shfl_xor_sync(FULLM, m2, off);
                    int   bj2 = __shfl_xor_sync(FULLM, j2, off);
                    if (b1 < m1 || (b1 == m1 && bj1 < j1)) {
                        if (m1 < b2 || (m1 == b2 && j1 < bj2)) { m2 = m1; j2 = j1; }
                        else { m2 = b2; j2 = bj2; }
                        m1 = b1; j1 = bj1;
                    } else {
                        if (b1 < m2 || (b1 == m2 && bj1 < j2)) { m2 = b1; j2 = bj1; }
                    }
                }
                bool strict = (m1 < m2);
                int jt = j1;
                int i0 = row4col[jt];
                if (!strict && i0 >= 0) { jt = j2; i0 = row4col[jt]; }
                if (i0 >= 0) {
                    if (strict) idx--;
                    else if (cnt < 4 * G) cnt++;
                }
                if (lane == 0) {
                    u_sh[i] = m2;
                    if (strict) v_sh[jt] -= (m2 - m1);
                    row4col[jt] = (short)i; col4row[i] = (short)jt;
                    if (i0 >= 0) {
                        col4row[i0] = -1;
                        if (strict) freerows[idx] = (short)i0;
                        else if (cnt - 1 < 4 * G) freerows[cnt - 1] = (short)i0;
                    }
                }
                __syncwarp();
            }
        }

        // ---- P4: sparse SAP on candidates ----
        for (int cur = 0; cur < G; cur++) {
            if (fail_sh) break;
            if (col4row[cur] >= 0) continue;
            if (lane == 0) nt_sh = 0;
            __syncwarp();

            int i = cur, sink = -1;
            float minVal = 0.f;

            while (true) {
                float ui = u_sh[i];
#pragma unroll
                for (int h = 0; h < 2; h++) {
                    int t = lane + 32 * h;
                    int j = cand_col[i * KC + t];
                    if (!used[j]) {
                        float r = minVal + cand_cost[i * KC + t] - ui - v_sh[j];
                        if (r < spc[j]) {
                            if (spc[j] == FINF) {
                                int slot = atomicAdd(&nt_sh, 1);
                                if (slot < TCAP) touched[slot] = (short)j;
                                else fail_sh = 1;
                            }
                            spc[j] = r; path[j] = (short)i;
                        }
                    }
                }
                __syncwarp();
                if (fail_sh) break;
                int nt = nt_sh;
                float best = FINF; int bestj = 0x7FFFFFFF;
                for (int t = lane; t < nt; t += 32) {
                    int j = touched[t];
                    if (!used[j]) {
                        float s = spc[j];
                        if (s < best || (s == best && j < bestj)) { best = s; bestj = j; }
                    }
                }
#pragma unroll
                for (int off = 16; off > 0; off >>= 1) {
                    float ob = __shfl_down_sync(FULLM, best, off);
                    int   oj = __shfl_down_sync(FULLM, bestj, off);
                    if (ob < best || (ob == best && oj < bestj)) { best = ob; bestj = oj; }
                }
                best  = __shfl_sync(FULLM, best, 0);
                bestj = __shfl_sync(FULLM, bestj, 0);
                if (best == FINF) { fail_sh = 1; break; }   // sparse dead-end -> repair
                minVal = best;
                int j1 = bestj;
                if (lane == 0) used[j1] = 1;
                __syncwarp();
                int nr = row4col[j1];
                if (nr < 0) { sink = j1; break; }
                i = nr;
            }
            if (fail_sh) break;   // dirty spc/used repaired by full reinit later

            int nt = nt_sh;
            if (lane == 0) u_sh[cur] += minVal;
            for (int t = lane; t < nt; t += 32) {
                int j = touched[t];
                if (used[j]) {
                    float d = minVal - spc[j];
                    int r = row4col[j];
                    if (r >= 0) u_sh[r] += d;
                    v_sh[j] -= d;
                }
            }
            __syncwarp();
            if (lane == 0) {
                int j = sink;
                while (true) {
                    int i2 = path[j];
                    row4col[j] = (short)i2;
                    int tcol = col4row[i2];
                    col4row[i2] = (short)j;
                    j = tcol;
                    if (i2 == cur) break;
                }
            }
            __syncwarp();
            for (int t = lane; t < nt && t < TCAP; t += 32) {
                int j = touched[t]; spc[j] = FINF; used[j] = 0;
            }
            __syncwarp();
        }
    }
    __syncthreads();

    // =================== VERIFY: full-row reduced minima (8 warps) ===================
    for (int r = wid; r < G; r += 8) {
        const float* crow = C + (size_t)r * Q;
        float best = FINF; int bj = Q;
        for (int j = lane; j < Q; j += 32) {
            float red = __ldg(&crow[j]) - v_sh[j];
            if (red < best) { best = red; bj = j; }
        }
#pragma unroll
        for (int off = 16; off > 0; off >>= 1) {
            float ob = __shfl_down_sync(FULLM, best, off);
            int   oj = __shfl_down_sync(FULLM, bj, off);
            if (ob < best || (ob == best && oj < bj)) { best = ob; bj = oj; }
        }
        if (lane == 0) { umin[r] = best; uarg[r] = bj; }
    }
    __syncthreads();

    // free rows that lost complementary slackness; try greedy tight reassign
    if (tid == 0) {
        int nf = 0;
        for (int r = 0; r < G; r++) {
            int jc = col4row[r];
            if (jc < 0) {
                u_sh[r] = umin[r];
                int j = uarg[r];
                if (row4col[j] < 0) { row4col[j] = (short)r; col4row[r] = (short)j; }
                else freerows[nf++] = (short)r;
            } else if (umin[r] < u_sh[r]) {
                row4col[jc] = -1; col4row[r] = -1;
                u_sh[r] = umin[r];
                int j = uarg[r];
                if (row4col[j] < 0) { row4col[j] = (short)r; col4row[r] = (short)j; }
                else freerows[nf++] = (short)r;
            }
        }
        nfree_sh = nf;
    }
    __syncthreads();

    // =================== REPAIR: full-width SAP for freed rows only ===================
    for (int k = 0; k < nfree_sh; k++) {
        int cur = freerows[k];
        if (col4row[cur] >= 0) continue;
        for (int j = tid; j < Q; j += HT) { spc[j] = FINF; used[j] = 0; }
        __syncthreads();

        int i = cur, par = 0, sink = -1;
        float minVal = 0.f;

        while (true) {
            float ui = u_sh[i];
            const float* crow = C + (size_t)i * Q;
            float best = FINF; int bestj = 0x7FFFFFFF;
            for (int j = tid; j < Q; j += HT) {
                if (!used[j]) {
                    float r = minVal + __ldg(&crow[j]) - ui - v_sh[j];
                    if (r < spc[j]) { spc[j] = r; path[j] = (short)i; }
                    float s = spc[j];
                    if (s < best) { best = s; bestj = j; }
                }
            }
#pragma unroll
            for (int off = 16; off > 0; off >>= 1) {
                float ob = __shfl_down_sync(FULLM, best, off);
                int   oj = __shfl_down_sync(FULLM, bestj, off);
                if (ob < best || (ob == best && oj < bestj)) { best = ob; bestj = oj; }
            }
            if (lane == 0) { red_val[par][wid] = best; red_idx[par][wid] = bestj; }
            __syncthreads();
            best = red_val[par][0]; bestj = red_idx[par][0];
#pragma unroll
            for (int w = 1; w < 8; w++) {
                float ob = red_val[par][w]; int oj = red_idx[par][w];
                if (ob < best || (ob == best && oj < bestj)) { best = ob; bestj = oj; }
            }
            minVal = best;
            int j1 = bestj;
            if ((j1 & (HT - 1)) == tid) used[j1] = 1;
            par ^= 1;
            __syncthreads();     // used[j1] visible before next relax
            int nr = row4col[j1];
            if (nr < 0) { sink = j1; break; }
            i = nr;
        }

        for (int j = tid; j < Q; j += HT) {
            if (used[j]) {
                float d = minVal - spc[j];
                int r = row4col[j];
                if (r >= 0) u_sh[r] += d;
                v_sh[j] -= d;
            }
        }
        __syncthreads();
        if (tid == 0) {
            u_sh[cur] += minVal;
            int j = sink;
            while (true) {
                int i2 = path[j];
                row4col[j] = (short)i2;
                int tcol = col4row[i2];
                col4row[i2] = (short)j;
                j = tcol;
                if (i2 == cur) break;
            }
        }
        __syncthreads();
    }

    // =================== fused per-batch losses (fp64) ===================
    double cls = 0.0, bbox = 0.0, gio = 0.0;
    for (int q = tid; q < Q; q += HT) {
        float l0 = pl[((size_t)b * Q + q) * 2 + 0];
        float l1 = pl[((size_t)b * Q + q) * 2 + 1];
        float mx = fmaxf(l0, l1);
        float lse = mx + logf(expf(l0 - mx) + expf(l1 - mx));
        cls += 0.1 * (double)(lse - l1);
    }
    if (tid < G) {
        int g = tid;
        int q = col4row[g];
        const float4 mp = *reinterpret_cast<const float4*>(pb + ((size_t)b * Q + q) * 4);
        const float4 mg = *reinterpret_cast<const float4*>(gb + ((size_t)b * G + g) * 4);
        bbox = (double)(fabsf(mp.x - mg.x) + fabsf(mp.y - mg.y) +
                        fabsf(mp.z - mg.z) + fabsf(mp.w - mg.w));
        gio = 1.0 - (double)giou_ok(mp.x, mp.y, mp.z, mp.w, mg.x, mg.y, mg.z, mg.w);
        float l0 = pl[((size_t)b * Q + q) * 2 + 0];
        float l1 = pl[((size_t)b * Q + q) * 2 + 1];
        float mx = fmaxf(l0, l1);
        float lse = mx + logf(expf(l0 - mx) + expf(l1 - mx));
        cls += (double)(lse - l0) - 0.1 * (double)(lse - l1);
    }
#pragma unroll
    for (int off = 16; off > 0; off >>= 1) {
        cls  += __shfl_down_sync(FULLM, cls, off);
        bbox += __shfl_down_sync(FULLM, bbox, off);
        gio  += __shfl_down_sync(FULLM, gio, off);
    }
    if (lane == 0) { wsum[wid][0] = cls; wsum[wid][1] = bbox; wsum[wid][2] = gio; }
    __syncthreads();

    if (tid == 0) {
        double cls_t = 0.0, bbox_t = 0.0, gio_t = 0.0;
        for (int w = 0; w < 8; w++) {
            cls_t += wsum[w][0]; bbox_t += wsum[w][1]; gio_t += wsum[w][2];
        }
        g_part[b * 3 + 0] = cls_t;
        g_part[b * 3 + 1] = bbox_t;
        g_part[b * 3 + 2] = gio_t;
        __threadfence();
        int prev = atomicAdd(&g_done, 1);
        if (prev == B - 1) {
            g_done = 0;
            __threadfence();
            double csum = 0.0, bsum = 0.0, gsum = 0.0;
            for (int k = 0; k < B; k++) {
                csum += g_part[k * 3 + 0];
                bsum += g_part[k * 3 + 1];
                gsum += g_part[k * 3 + 2];
            }
            const double wt_sum = 64.0 + (double)(Q - G) * 0.1;  // 157.6
            double lc = (csum / wt_sum) / (double)B;
            double nb = (double)(B * G);
            double lb = bsum / nb;
            double lg = gsum / nb;
            out[0] = (float)(1.0 * lc + 5.0 * lb + 2.0 * lg);
            out[1] = (float)lc;
            out[2] = (float)lb;
            out[3] = (float)lg;
        }
    }
}

// ---------------------------------------------------------------------------
extern "C" void kernel_launch(void* const* d_in, const int* in_sizes, int n_in,
                              void* d_out, int out_size) {
    const float* pred_boxes  = (const float*)d_in[0];  // [32,1000,4]
    const float* pred_logits = (const float*)d_in[1];  // [32,1000,2]
    const float* gt_boxes    = (const float*)d_in[2];  // [32,64,4]
    float* out = (float*)d_out;

    dim3 cgrid((Q + 127) / 128, G / 4, B);
    cost_kernel<<<cgrid, 128>>>(pred_boxes, pred_logits, gt_boxes);
    hungarian_kernel<<<B, HT>>>(pred_boxes, pred_logits, gt_boxes, out);
}

// round 7
// speedup vs baseline: 4.2904x; 1.0947x over previous
#include <cuda_runtime.h>
#include <math.h>
#include <float.h>

#define B 32
#define Q 1000
#define G 64
#define HT 256
#define FR_CAP 256
#define FULLM 0xffffffffu

__device__ double g_part[B * 3];   // per-batch {cls, bbox, giou}
__device__ int    g_done = 0;

// ---------------------------------------------------------------------------
// giou used in the matching cost (same formula as R6's cost_kernel — passed)
__device__ __forceinline__ float giou_fast(float ax1, float ay1, float ax2, float ay2,
                                           float bx1, float by1, float bx2, float by2) {
    float ix1 = fmaxf(ax1, bx1), iy1 = fmaxf(ay1, by1);
    float ix2 = fminf(ax2, bx2), iy2 = fminf(ay2, by2);
    float inter  = fmaxf(ix2 - ix1, 0.f) * fmaxf(iy2 - iy1, 0.f);
    float area_a = fmaxf(ax2 - ax1, 0.f) * fmaxf(ay2 - ay1, 0.f);
    float area_b = fmaxf(bx2 - bx1, 0.f) * fmaxf(by2 - by1, 0.f);
    float uni = area_a + area_b - inter + 1e-6f;
    float iou = __fdividef(inter, uni);
    float ex1 = fminf(ax1, bx1), ey1 = fminf(ay1, by1);
    float ex2 = fmaxf(ax2, bx2), ey2 = fmaxf(ay2, by2);
    float enc = fmaxf(fmaxf(ex2 - ex1, 0.f) * fmaxf(ey2 - ey1, 0.f), 1e-6f);
    return iou - __fdividef(enc - uni, enc);
}

// precise version for the loss (matches reference math)
__device__ __forceinline__ float giou_ok(float ax1, float ay1, float ax2, float ay2,
                                         float bx1, float by1, float bx2, float by2) {
    float ix1 = fmaxf(ax1, bx1), iy1 = fmaxf(ay1, by1);
    float ix2 = fminf(ax2, bx2), iy2 = fminf(ay2, by2);
    float inter  = fmaxf(ix2 - ix1, 0.f) * fmaxf(iy2 - iy1, 0.f);
    float area_a = fmaxf(ax2 - ax1, 0.f) * fmaxf(ay2 - ay1, 0.f);
    float area_b = fmaxf(bx2 - bx1, 0.f) * fmaxf(by2 - by1, 0.f);
    float uni = area_a + area_b - inter + 1e-6f;
    float iou = inter / uni;
    float ex1 = fminf(ax1, bx1), ey1 = fminf(ay1, by1);
    float ex2 = fmaxf(ax2, bx2), ey2 = fmaxf(ay2, by2);
    float enc = fmaxf(fmaxf(ex2 - ex1, 0.f) * fmaxf(ey2 - ey1, 0.f), 1e-6f);
    return iou - (enc - uni) / enc;
}

// ---------------------------------------------------------------------------
// One fused kernel: inputs->smem, compute-on-the-fly LAPJV, losses, finalize.
// ---------------------------------------------------------------------------
__global__ void __launch_bounds__(HT, 1) match_kernel(
        const float* __restrict__ pb, const float* __restrict__ pl,
        const float* __restrict__ gb, float* __restrict__ out) {
    const int b = blockIdx.x;
    const int tid = threadIdx.x;
    const int lane = tid & 31, wid = tid >> 5;
    const float FINF = FLT_MAX;

    // ---- smem: batch inputs (SoA) + LAPJV state (~36 KB) ----
    __shared__ float  pbx[Q], pby[Q], pbz[Q], pbw[Q];
    __shared__ float  base[Q];          // -prob0[j]
    __shared__ float4 gt4s[G];
    __shared__ float  v_sh[Q];
    __shared__ float  spc[Q];
    __shared__ float  u_sh[G];
    __shared__ short  path[Q];
    __shared__ short  row4col[Q];
    __shared__ short  col4row[G];
    __shared__ unsigned char used[Q];
    __shared__ float  umin[G];
    __shared__ int    uarg[G];
    __shared__ short  freerows[FR_CAP];
    __shared__ float  red_m1[2][8], red_m2[2][8];
    __shared__ int    red_j1[2][8], red_j2[2][8];
    __shared__ double wsum[8][3];
    __shared__ int    nfree_sh;

    // ---- load inputs, init state ----
    for (int j = tid; j < Q; j += HT) {
        float4 p = *reinterpret_cast<const float4*>(pb + ((size_t)b * Q + j) * 4);
        pbx[j] = p.x; pby[j] = p.y; pbz[j] = p.z; pbw[j] = p.w;
        float l0 = pl[((size_t)b * Q + j) * 2 + 0];
        float l1 = pl[((size_t)b * Q + j) * 2 + 1];
        base[j] = -1.0f / (1.0f + __expf(l1 - l0));   // -softmax[0]
        v_sh[j] = 0.f; row4col[j] = -1; spc[j] = FINF; used[j] = 0;
    }
    if (tid < G)
        gt4s[tid] = *reinterpret_cast<const float4*>(gb + ((size_t)b * G + tid) * 4);
    __syncthreads();

    // on-the-fly cost: C[i][j] = base[j] + 5*L1 - 2*giou
    auto costf = [&](int j, float4 g) -> float {
        float px1 = pbx[j], py1 = pby[j], px2 = pbz[j], pw2 = pbw[j];
        float l1c = fabsf(px1 - g.x) + fabsf(py1 - g.y) +
                    fabsf(px2 - g.z) + fabsf(pw2 - g.w);
        float gi = giou_fast(px1, py1, px2, pw2, g.x, g.y, g.z, g.w);
        return base[j] + 5.0f * l1c - 2.0f * gi;
    };

    // ---- P1: row minima, warp-per-row (8 rows in flight) ----
    for (int r = wid; r < G; r += 8) {
        float4 g = gt4s[r];
        float best = FINF; int bj = Q;
        for (int j = lane; j < Q; j += 32) {
            float c = costf(j, g);
            if (c < best) { best = c; bj = j; }
        }
#pragma unroll
        for (int off = 16; off > 0; off >>= 1) {
            float om = __shfl_down_sync(FULLM, best, off);
            int   oj = __shfl_down_sync(FULLM, bj, off);
            if (om < best || (om == best && oj < bj)) { best = om; bj = oj; }
        }
        if (lane == 0) { umin[r] = best; uarg[r] = bj; }
    }
    __syncthreads();
    if (tid < G) u_sh[tid] = umin[tid];
    // ---- P2: greedy tight-edge assignment ----
    if (tid == 0) {
        int nf = 0;
        for (int r = 0; r < G; r++) {
            int j = uarg[r];
            if (row4col[j] < 0) { row4col[j] = (short)r; col4row[r] = (short)j; }
            else { col4row[r] = -1; freerows[nf++] = (short)r; }
        }
        nfree_sh = nf;
    }
    __syncthreads();

    // ---- P3: augmenting row reduction, 256-wide, compute-on-the-fly ----
    {
        int idx = 0, cnt = nfree_sh, iters = 0, par = 0;
        while (idx < cnt && iters < 192) {
            iters++;
            int i = freerows[idx]; idx++;
            float4 g = gt4s[i];
            float m1 = FINF, m2 = FINF; int j1 = Q, j2 = Q;
            for (int j = tid; j < Q; j += HT) {
                float red = costf(j, g) - v_sh[j];
                if (red < m1)      { m2 = m1; j2 = j1; m1 = red; j1 = j; }
                else if (red < m2) { m2 = red; j2 = j; }
            }
#pragma unroll
            for (int off = 16; off > 0; off >>= 1) {
                float b1 = __shfl_xor_sync(FULLM, m1, off);
                int  bj1 = __shfl_xor_sync(FULLM, j1, off);
                float b2 = __shfl_xor_sync(FULLM, m2, off);
                int  bj2 = __shfl_xor_sync(FULLM, j2, off);
                if (b1 < m1 || (b1 == m1 && bj1 < j1)) {
                    if (m1 < b2 || (m1 == b2 && j1 < bj2)) { m2 = m1; j2 = j1; }
                    else { m2 = b2; j2 = bj2; }
                    m1 = b1; j1 = bj1;
                } else {
                    if (b1 < m2 || (b1 == m2 && bj1 < j2)) { m2 = b1; j2 = bj1; }
                }
            }
            if (lane == 0) {
                red_m1[par][wid] = m1; red_j1[par][wid] = j1;
                red_m2[par][wid] = m2; red_j2[par][wid] = j2;
            }
            __syncthreads();
            m1 = red_m1[par][0]; j1 = red_j1[par][0];
            m2 = red_m2[par][0]; j2 = red_j2[par][0];
#pragma unroll
            for (int k = 1; k < 8; k++) {
                float b1 = red_m1[par][k]; int bj1 = red_j1[par][k];
                float b2 = red_m2[par][k]; int bj2 = red_j2[par][k];
                if (b1 < m1 || (b1 == m1 && bj1 < j1)) {
                    if (m1 < b2 || (m1 == b2 && j1 < bj2)) { m2 = m1; j2 = j1; }
                    else { m2 = b2; j2 = bj2; }
                    m1 = b1; j1 = bj1;
                } else {
                    if (b1 < m2 || (b1 == m2 && bj1 < j2)) { m2 = b1; j2 = bj1; }
                }
            }
            // decision (identical on all threads)
            bool strict = (m1 < m2);
            int jt = j1;
            int i0 = row4col[jt];
            if (!strict && i0 >= 0 && j2 < Q) { jt = j2; i0 = row4col[jt]; }
            if (i0 >= 0) {
                if (strict) idx--;
                else if (cnt < FR_CAP) cnt++;
            }
            if (tid == 0) {
                u_sh[i] = m2;
                if (strict) v_sh[jt] -= (m2 - m1);
                row4col[jt] = (short)i; col4row[i] = (short)jt;
                if (i0 >= 0) {
                    col4row[i0] = -1;
                    if (strict) freerows[idx] = (short)i0;
                    else if (cnt - 1 < FR_CAP) freerows[cnt - 1] = (short)i0;
                }
            }
            par ^= 1;
            __syncthreads();
        }
    }

    // ---- P4: SAP (256-wide, compute-on-the-fly) for remaining free rows ----
    for (int cur = 0; cur < G; cur++) {
        if (col4row[cur] >= 0) continue;

        int i = cur, par = 0, sink = -1;
        float minVal = 0.f;

        while (true) {
            float ui = u_sh[i];
            float4 g = gt4s[i];
            float best = FINF; int bestj = 0x7FFFFFFF;
            for (int j = tid; j < Q; j += HT) {
                if (!used[j]) {
                    float r = minVal + costf(j, g) - ui - v_sh[j];
                    if (r < spc[j]) { spc[j] = r; path[j] = (short)i; }
                    float s = spc[j];
                    if (s < best) { best = s; bestj = j; }
                }
            }
#pragma unroll
            for (int off = 16; off > 0; off >>= 1) {
                float ob = __shfl_down_sync(FULLM, best, off);
                int   oj = __shfl_down_sync(FULLM, bestj, off);
                if (ob < best || (ob == best && oj < bestj)) { best = ob; bestj = oj; }
            }
            if (lane == 0) { red_m1[par][wid] = best; red_j1[par][wid] = bestj; }
            __syncthreads();
            best = red_m1[par][0]; bestj = red_j1[par][0];
#pragma unroll
            for (int w = 1; w < 8; w++) {
                float ob = red_m1[par][w]; int oj = red_j1[par][w];
                if (ob < best || (ob == best && oj < bestj)) { best = ob; bestj = oj; }
            }
            minVal = best;
            int j1 = bestj;
            if ((j1 & (HT - 1)) == tid) used[j1] = 1;   // owner-private flag
            par ^= 1;
            int nr = row4col[j1];
            if (nr < 0) { sink = j1; break; }
            i = nr;
        }
        __syncthreads();

        // dual updates (parallel; distinct rows per used column -> race-free)
        for (int j = tid; j < Q; j += HT) {
            if (used[j]) {
                float d = minVal - spc[j];
                int r = row4col[j];
                if (r >= 0) u_sh[r] += d;
                v_sh[j] -= d;
            }
        }
        __syncthreads();
        if (tid == 0) {
            u_sh[cur] += minVal;
            int j = sink;
            while (true) {
                int i2 = path[j];
                row4col[j] = (short)i2;
                int tcol = col4row[i2];
                col4row[i2] = (short)j;
                j = tcol;
                if (i2 == cur) break;
            }
        }
        // reset search state (owner-private writes; disjoint from flip arrays)
        for (int j = tid; j < Q; j += HT) { spc[j] = FINF; used[j] = 0; }
        __syncthreads();
    }

    // ---- fused per-batch losses (fp64) ----
    double cls = 0.0, bbox = 0.0, gio = 0.0;
    for (int q = tid; q < Q; q += HT) {
        float l0 = pl[((size_t)b * Q + q) * 2 + 0];
        float l1 = pl[((size_t)b * Q + q) * 2 + 1];
        float mx = fmaxf(l0, l1);
        float lse = mx + logf(expf(l0 - mx) + expf(l1 - mx));
        cls += 0.1 * (double)(lse - l1);
    }
    if (tid < G) {
        int g = tid;
        int q = col4row[g];
        float4 mg = gt4s[g];
        float mpx = pbx[q], mpy = pby[q], mpz = pbz[q], mpw = pbw[q];
        bbox = (double)(fabsf(mpx - mg.x) + fabsf(mpy - mg.y) +
                        fabsf(mpz - mg.z) + fabsf(mpw - mg.w));
        gio = 1.0 - (double)giou_ok(mpx, mpy, mpz, mpw, mg.x, mg.y, mg.z, mg.w);
        float l0 = pl[((size_t)b * Q + q) * 2 + 0];
        float l1 = pl[((size_t)b * Q + q) * 2 + 1];
        float mx = fmaxf(l0, l1);
        float lse = mx + logf(expf(l0 - mx) + expf(l1 - mx));
        cls += (double)(lse - l0) - 0.1 * (double)(lse - l1);
    }
#pragma unroll
    for (int off = 16; off > 0; off >>= 1) {
        cls  += __shfl_down_sync(FULLM, cls, off);
        bbox += __shfl_down_sync(FULLM, bbox, off);
        gio  += __shfl_down_sync(FULLM, gio, off);
    }
    if (lane == 0) { wsum[wid][0] = cls; wsum[wid][1] = bbox; wsum[wid][2] = gio; }
    __syncthreads();

    if (tid == 0) {
        double cls_t = 0.0, bbox_t = 0.0, gio_t = 0.0;
        for (int w = 0; w < 8; w++) {
            cls_t += wsum[w][0]; bbox_t += wsum[w][1]; gio_t += wsum[w][2];
        }
        g_part[b * 3 + 0] = cls_t;
        g_part[b * 3 + 1] = bbox_t;
        g_part[b * 3 + 2] = gio_t;
        __threadfence();
        int prev = atomicAdd(&g_done, 1);
        if (prev == B - 1) {
            g_done = 0;
            __threadfence();
            double csum = 0.0, bsum = 0.0, gsum = 0.0;
            for (int k = 0; k < B; k++) {
                csum += g_part[k * 3 + 0];
                bsum += g_part[k * 3 + 1];
                gsum += g_part[k * 3 + 2];
            }
            const double wt_sum = 64.0 + (double)(Q - G) * 0.1;  // 157.6
            double lc = (csum / wt_sum) / (double)B;
            double nb = (double)(B * G);
            double lb = bsum / nb;
            double lg = gsum / nb;
            out[0] = (float)(1.0 * lc + 5.0 * lb + 2.0 * lg);
            out[1] = (float)lc;
            out[2] = (float)lb;
            out[3] = (float)lg;
        }
    }
}

// ---------------------------------------------------------------------------
extern "C" void kernel_launch(void* const* d_in, const int* in_sizes, int n_in,
                              void* d_out, int out_size) {
    const float* pred_boxes  = (const float*)d_in[0];  // [32,1000,4]
    const float* pred_logits = (const float*)d_in[1];  // [32,1000,2]
    const float* gt_boxes    = (const float*)d_in[2];  // [32,64,4]
    float* out = (float*)d_out;

    match_kernel<<<B, HT>>>(pred_boxes, pred_logits, gt_boxes, out);
}